// round 10
// baseline (speedup 1.0000x reference)
#include <cuda_runtime.h>
#include <cuda_bf16.h>
#include <math.h>
#include <stdint.h>

#define HID   2048
#define NB    2
#define SQ    2048
#define NHEAD 16
#define HD    128
#define MROWS (NB * SQ)        /* 4096 */
#define NW    (HID * HID)      /* 4194304 */
#define KDIM  2048

/* ---------------- scratch (device globals; no allocation allowed) -------- */
__device__ __nv_bfloat16 g_Wh[4][NW];
__device__ __nv_bfloat16 g_Wl[4][NW];
__device__ __nv_bfloat16 g_Xh[MROWS * HID];
__device__ __nv_bfloat16 g_Xl[MROWS * HID];
__device__ __nv_bfloat16 g_Ah[MROWS * HID];
__device__ __nv_bfloat16 g_Al[MROWS * HID];
__device__ float g_Q[MROWS * HID];
__device__ float g_K[MROWS * HID];
__device__ float g_V[MROWS * HID];

__device__ __forceinline__ uint32_t smem_u32(const void* p) {
    uint32_t a;
    asm("{ .reg .u64 t; cvta.to.shared.u64 t, %1; cvt.u32.u64 %0, t; }"
        : "=r"(a) : "l"(p));
    return a;
}
__device__ __forceinline__ void ldm_x4(uint32_t* r, uint32_t addr) {
    asm volatile("ldmatrix.sync.aligned.m8n8.x4.shared.b16 {%0,%1,%2,%3}, [%4];"
                 : "=r"(r[0]), "=r"(r[1]), "=r"(r[2]), "=r"(r[3]) : "r"(addr));
}
__device__ __forceinline__ void mma_bf16(float* d, const uint32_t* a,
                                         uint32_t b0, uint32_t b1) {
    asm volatile("mma.sync.aligned.m16n8k16.row.col.f32.bf16.bf16.f32 "
                 "{%0,%1,%2,%3},{%4,%5,%6,%7},{%8,%9},{%0,%1,%2,%3};"
                 : "+f"(d[0]), "+f"(d[1]), "+f"(d[2]), "+f"(d[3])
                 : "r"(a[0]), "r"(a[1]), "r"(a[2]), "r"(a[3]), "r"(b0), "r"(b1));
}
__device__ __forceinline__ void split4(float4 v, uint2& hi, uint2& lo) {
    __nv_bfloat162 h0 = __float22bfloat162_rn(make_float2(v.x, v.y));
    __nv_bfloat162 h1 = __float22bfloat162_rn(make_float2(v.z, v.w));
    float2 f0 = __bfloat1622float2(h0), f1 = __bfloat1622float2(h1);
    __nv_bfloat162 l0 = __float22bfloat162_rn(make_float2(v.x - f0.x, v.y - f0.y));
    __nv_bfloat162 l1 = __float22bfloat162_rn(make_float2(v.z - f1.x, v.w - f1.y));
    hi = make_uint2(*(uint32_t*)&h0, *(uint32_t*)&h1);
    lo = make_uint2(*(uint32_t*)&l0, *(uint32_t*)&l1);
}
__device__ __forceinline__ uint32_t pack_hi(float a, float b) {
    __nv_bfloat162 h = __float22bfloat162_rn(make_float2(a, b));
    return *(uint32_t*)&h;
}
__device__ __forceinline__ uint32_t pack_lo(float a, float b, uint32_t hi) {
    float2 f = __bfloat1622float2(*(__nv_bfloat162*)&hi);
    __nv_bfloat162 l = __float22bfloat162_rn(make_float2(a - f.x, b - f.y));
    return *(uint32_t*)&l;
}
__device__ __forceinline__ void cp16(uint32_t smem, const void* g) {
    asm volatile("cp.async.cg.shared.global [%0], [%1], 16;"
                 :: "r"(smem), "l"(g) : "memory");
}
__device__ __forceinline__ void cp_commit() {
    asm volatile("cp.async.commit_group;" ::: "memory");
}
template <int N>
__device__ __forceinline__ void cp_wait() {
    asm volatile("cp.async.wait_group %0;" :: "n"(N) : "memory");
}

/* ---------------- weight reconstruction -> bf16 hi/lo -------------------- */
__global__ void build_weights(const float* __restrict__ cpq,
                              const float* __restrict__ cpk,
                              const float* __restrict__ cpv,
                              const float* __restrict__ cpo,
                              int ncp) {
    int i = blockIdx.x * 256 + threadIdx.x;
    if (i >= NW) return;
    const float dT = 1.0f / (float)(NW - 1);
    const float dX = 1.0f / (float)(ncp - 1);
    float t = (float)i * dT;
    int j = (int)((double)t * (double)(ncp - 1));
    if (j > ncp - 2) j = ncp - 2;
    if (j < 0) j = 0;
    while (j < ncp - 2 && (float)(j + 1) * dX <= t) j++;
    while (j > 0 && (float)j * dX > t) j--;
    float x0 = (float)j * dX;
    float x1 = (float)(j + 1) * dX;
    float f  = (t - x0) / (x1 - x0);
    const float* cps[4] = {cpq, cpk, cpv, cpo};
#pragma unroll
    for (int w = 0; w < 4; w++) {
        float a = cps[w][j];
        float val = fmaf(cps[w][j + 1] - a, f, a);
        __nv_bfloat16 hb = __float2bfloat16_rn(val);
        g_Wh[w][i] = hb;
        g_Wl[w][i] = __float2bfloat16_rn(val - __bfloat162float(hb));
    }
}

/* ---------------- split hidden_states -> bf16 hi/lo ---------------------- */
__global__ void split_x(const float* __restrict__ x) {
    int i = blockIdx.x * 256 + threadIdx.x;
    if (i >= MROWS * HID / 4) return;
    float4 v = *(const float4*)(x + 4 * (size_t)i);
    uint2 hi, lo; split4(v, hi, lo);
    *(uint2*)(g_Xh + 4 * (size_t)i) = hi;
    *(uint2*)(g_Xl + 4 * (size_t)i) = lo;
}

/* == bf16x3 HMMA GEMM, CTA 128x128, 512 thr, warp 32x32, frag pipeline === */
#define KC      32
#define NCHUNK  (KDIM / KC)
#define SA      40                      /* halfwords per smem row (80 B)    */
#define OFF_AH  0
#define OFF_AL  (128 * SA)
#define OFF_BH  (2 * 128 * SA)
#define OFF_BL  (3 * 128 * SA)
#define STG_HW  (4 * 128 * SA)          /* 20480 halfwords                  */
#define STG_B   (STG_HW * 2)            /* 40960 B                          */
#define NSTAGE  3
#define GEMM_SMEM (NSTAGE * STG_B)      /* 122880 B                         */

__global__ void __launch_bounds__(512, 1) gemm_hmma(const __nv_bfloat16* __restrict__ Ah,
                                                    const __nv_bfloat16* __restrict__ Al,
                                                    const __nv_bfloat16* __restrict__ Bh,
                                                    const __nv_bfloat16* __restrict__ Bl,
                                                    float* __restrict__ C) {
    extern __shared__ char shg[];
    const uint32_t sb = smem_u32(shg);
    const int tid = threadIdx.x;
    const int lane = tid & 31, wid = tid >> 5;
    const int warp_m = wid >> 2;              /* 0..3 : 32-row band         */
    const int warp_n = wid & 3;               /* 0..3 : 32-col band         */
    const int m0 = blockIdx.y * 128, n0 = blockIdx.x * 128;

    /* cp.async coords: 512 thr cover 128 rows x 32 cols per tile */
    const int rA = tid >> 2;                  /* 0..127                     */
    const int cA = (tid & 3) << 3;            /* bf16 col 0,8,16,24         */
    const __nv_bfloat16* gAh = Ah + (size_t)(m0 + rA) * KDIM + cA;
    const __nv_bfloat16* gAl = Al + (size_t)(m0 + rA) * KDIM + cA;
    const __nv_bfloat16* gBh = Bh + (size_t)(n0 + rA) * KDIM + cA;
    const __nv_bfloat16* gBl = Bl + (size_t)(n0 + rA) * KDIM + cA;
    const uint32_t dst = sb + (uint32_t)(rA * SA + cA) * 2;

    float acc[2][4][4];
#pragma unroll
    for (int i = 0; i < 2; i++)
#pragma unroll
        for (int j = 0; j < 4; j++)
#pragma unroll
            for (int q = 0; q < 4; q++) acc[i][j][q] = 0.0f;

    /* ldmatrix lane addressing */
    const int rowA = lane & 15, colA8 = (lane >= 16) ? 8 : 0;
    const int rowB = (lane & 7) + ((lane >= 16) ? 8 : 0);
    const int colB8 = (lane & 8) ? 8 : 0;
    const uint32_t aoff = (uint32_t)((warp_m * 32 + rowA) * SA + colA8) * 2;
    const uint32_t boff = (uint32_t)((warp_n * 32 + rowB) * SA + colB8) * 2;

    /* fragment double buffers */
    uint32_t fah[2][2][4], fal[2][2][4], fbh[2][2][4], fbl[2][2][4];

#define LOAD_SET(buf, stgbase, ks)                                           \
    do {                                                                     \
        const uint32_t ko = (uint32_t)((ks) * 16) * 2;                       \
        const uint32_t _tAh = (stgbase) + OFF_AH * 2;                        \
        const uint32_t _tAl = (stgbase) + OFF_AL * 2;                        \
        const uint32_t _tBh = (stgbase) + OFF_BH * 2;                        \
        const uint32_t _tBl = (stgbase) + OFF_BL * 2;                        \
        ldm_x4(fah[buf][0], _tAh + aoff + ko);                               \
        ldm_x4(fah[buf][1], _tAh + aoff + ko + (uint32_t)(16 * SA) * 2);     \
        ldm_x4(fal[buf][0], _tAl + aoff + ko);                               \
        ldm_x4(fal[buf][1], _tAl + aoff + ko + (uint32_t)(16 * SA) * 2);     \
        ldm_x4(fbh[buf][0], _tBh + boff + ko);                               \
        ldm_x4(fbh[buf][1], _tBh + boff + ko + (uint32_t)(16 * SA) * 2);     \
        ldm_x4(fbl[buf][0], _tBl + boff + ko);                               \
        ldm_x4(fbl[buf][1], _tBl + boff + ko + (uint32_t)(16 * SA) * 2);     \
    } while (0)

#define MMA_SET(buf)                                                         \
    do {                                                                     \
        /* term hh: 8 independent */                                         \
        _Pragma("unroll")                                                    \
        for (int g = 0; g < 2; g++)                                          \
            _Pragma("unroll")                                                \
            for (int mt = 0; mt < 2; mt++) {                                 \
                mma_bf16(acc[mt][2 * g],     fah[buf][mt], fbh[buf][g][0], fbh[buf][g][1]); \
                mma_bf16(acc[mt][2 * g + 1], fah[buf][mt], fbh[buf][g][2], fbh[buf][g][3]); \
            }                                                                \
        /* term hl */                                                        \
        _Pragma("unroll")                                                    \
        for (int g = 0; g < 2; g++)                                          \
            _Pragma("unroll")                                                \
            for (int mt = 0; mt < 2; mt++) {                                 \
                mma_bf16(acc[mt][2 * g],     fah[buf][mt], fbl[buf][g][0], fbl[buf][g][1]); \
                mma_bf16(acc[mt][2 * g + 1], fah[buf][mt], fbl[buf][g][2], fbl[buf][g][3]); \
            }                                                                \
        /* term lh */                                                        \
        _Pragma("unroll")                                                    \
        for (int g = 0; g < 2; g++)                                          \
            _Pragma("unroll")                                                \
            for (int mt = 0; mt < 2; mt++) {                                 \
                mma_bf16(acc[mt][2 * g],     fal[buf][mt], fbh[buf][g][0], fbh[buf][g][1]); \
                mma_bf16(acc[mt][2 * g + 1], fal[buf][mt], fbh[buf][g][2], fbh[buf][g][3]); \
            }                                                                \
    } while (0)

#define ISSUE_CP(chunk, stage)                                               \
    do {                                                                     \
        const uint32_t _st = sb - sb + (uint32_t)(stage) * STG_B;            \
        const int _kc = (chunk) * KC;                                        \
        cp16(dst + _st + OFF_AH * 2 - (sb - sb), gAh + _kc);                 \
        cp16(dst + _st + OFF_AL * 2, gAl + _kc);                             \
        cp16(dst + _st + OFF_BH * 2, gBh + _kc);                             \
        cp16(dst + _st + OFF_BL * 2, gBl + _kc);                             \
        cp_commit();                                                         \
    } while (0)

    /* prologue: chunks 0,1 in flight */
    ISSUE_CP(0, 0);
    ISSUE_CP(1, 1);
    cp_wait<1>();
    __syncthreads();
    LOAD_SET(0, sb + 0 * STG_B, 0);

    for (int c = 0; c < NCHUNK; c++) {
        const uint32_t stg_c = sb + (uint32_t)(c % 3) * STG_B;
        LOAD_SET(1, stg_c, 1);         /* (c, ks1) frags — covered by MMAs  */
        MMA_SET(0);                     /* (c, ks0)                          */
        if (c + 1 < NCHUNK) {
            cp_wait<0>();               /* chunk c+1 smem ready              */
            __syncthreads();
            if (c + 2 < NCHUNK) ISSUE_CP(c + 2, (c + 2) % 3);
            LOAD_SET(0, sb + (uint32_t)((c + 1) % 3) * STG_B, 0);
        }
        MMA_SET(1);                     /* (c, ks1) — covers next loads      */
    }

#undef LOAD_SET
#undef MMA_SET
#undef ISSUE_CP

    const int rowg = lane >> 2, colg = (lane & 3) * 2;
#pragma unroll
    for (int mt = 0; mt < 2; mt++) {
#pragma unroll
        for (int nt = 0; nt < 4; nt++) {
            int r = m0 + warp_m * 32 + mt * 16 + rowg;
            int cc = n0 + warp_n * 32 + nt * 8 + colg;
            *(float2*)(C + (size_t)r * KDIM + cc) =
                make_float2(acc[mt][nt][0], acc[mt][nt][1]);
            *(float2*)(C + (size_t)(r + 8) * KDIM + cc) =
                make_float2(acc[mt][nt][2], acc[mt][nt][3]);
        }
    }
}

/* ========== bf16x3 HMMA causal flash attention (unchanged from R9) ======= */
#define FKS 136
#define FVS 72
#define OFF_QH 0
#define OFF_QL (128 * FKS)
#define OFF_KH (2 * 128 * FKS)
#define OFF_KL (OFF_KH + 64 * FKS)
#define OFF_VH (OFF_KL + 64 * FKS)
#define OFF_VL (OFF_VH + 128 * FVS)
#define FL_SMEM ((OFF_VL + 128 * FVS) * 2)

__global__ void __launch_bounds__(256, 1) flash_hmma(const float* __restrict__ Q,
                                                     const float* __restrict__ Km,
                                                     const float* __restrict__ Vm) {
    extern __shared__ char shf[];
    __nv_bfloat16* s = (__nv_bfloat16*)shf;
    const uint32_t sb = smem_u32(shf);
    const int tid = threadIdx.x, lane = tid & 31, wid = tid >> 5;
    const int qb = blockIdx.x, h = blockIdx.y, b = blockIdx.z;
    const int q0 = qb * 128;
    const int wm0 = wid * 16;
    const float scale = 0.08838834764831845f;

    const float* Qg = Q + (size_t)(b * SQ + q0) * HID + h * HD;
#pragma unroll
    for (int it = 0; it < 16; it++) {
        int idx = tid + it * 256;
        int r = idx >> 5, c4 = (idx & 31) << 2;
        float4 v = *(const float4*)(Qg + (size_t)r * HID + c4);
        uint2 hi, lo; split4(v, hi, lo);
        *(uint2*)(s + OFF_QH + r * FKS + c4) = hi;
        *(uint2*)(s + OFF_QL + r * FKS + c4) = lo;
    }

    const uint32_t aBaseH = sb + 2u * (OFF_QH + (wm0 + (lane & 15)) * FKS + ((lane >> 4) << 3));
    const uint32_t aBaseL = sb + 2u * (OFF_QL + (wm0 + (lane & 15)) * FKS + ((lane >> 4) << 3));
    const int krow = (lane & 7) + ((lane >> 4) << 3);
    const uint32_t kBaseH = sb + 2u * (OFF_KH + krow * FKS + (lane & 8));
    const uint32_t kBaseL = sb + 2u * (OFF_KL + krow * FKS + (lane & 8));
    const uint32_t vBaseH = sb + 2u * (OFF_VH + krow * FVS + (lane & 8));
    const uint32_t vBaseL = sb + 2u * (OFF_VL + krow * FVS + (lane & 8));

    float acc_o[16][4];
#pragma unroll
    for (int i = 0; i < 16; i++)
#pragma unroll
        for (int j = 0; j < 4; j++) acc_o[i][j] = 0.0f;
    float m0r = -1e30f, m1r = -1e30f, l0r = 0.0f, l1r = 0.0f;

    const int kb_max = 2 * qb + 1;
    const int r0g = q0 + wm0 + (lane >> 2);
    const int r1g = r0g + 8;

    for (int kb = 0; kb <= kb_max; kb++) {
        const int k0 = kb * 64;
        __syncthreads();
        const float* Kg = Km + (size_t)(b * SQ + k0) * HID + h * HD;
#pragma unroll
        for (int it = 0; it < 8; it++) {
            int idx = tid + it * 256;
            int r = idx >> 5, c4 = (idx & 31) << 2;
            float4 v = *(const float4*)(Kg + (size_t)r * HID + c4);
            uint2 hi, lo; split4(v, hi, lo);
            *(uint2*)(s + OFF_KH + r * FKS + c4) = hi;
            *(uint2*)(s + OFF_KL + r * FKS + c4) = lo;
        }
        const float* Vg = Vm + (size_t)(b * SQ + k0) * HID + h * HD;
#pragma unroll
        for (int it = 0; it < 8; it++) {
            int idx = tid + it * 256;
            int r = idx & 63, c4 = (idx >> 6) << 2;
            float4 v = *(const float4*)(Vg + (size_t)r * HID + c4);
            float e[4] = {v.x, v.y, v.z, v.w};
#pragma unroll
            for (int q = 0; q < 4; q++) {
                __nv_bfloat16 hb = __float2bfloat16_rn(e[q]);
                __nv_bfloat16 lb = __float2bfloat16_rn(e[q] - __bfloat162float(hb));
                s[OFF_VH + (c4 + q) * FVS + r] = hb;
                s[OFF_VL + (c4 + q) * FVS + r] = lb;
            }
        }
        __syncthreads();

        if (k0 > q0 + wm0) continue;

        float accs[8][4];
#pragma unroll
        for (int i = 0; i < 8; i++)
#pragma unroll
            for (int j = 0; j < 4; j++) accs[i][j] = 0.0f;
#pragma unroll
        for (int ks = 0; ks < 8; ks++) {
            uint32_t ah[4], al[4];
            ldm_x4(ah, aBaseH + ks * 32);
            ldm_x4(al, aBaseL + ks * 32);
            uint32_t bh[4][4], bl[4][4];
#pragma unroll
            for (int ng = 0; ng < 4; ng++) {
                ldm_x4(bh[ng], kBaseH + (uint32_t)(ng * 16 * FKS) * 2 + ks * 32);
                ldm_x4(bl[ng], kBaseL + (uint32_t)(ng * 16 * FKS) * 2 + ks * 32);
            }
#pragma unroll
            for (int ng = 0; ng < 4; ng++) {
                mma_bf16(accs[2 * ng],     ah, bh[ng][0], bh[ng][1]);
                mma_bf16(accs[2 * ng + 1], ah, bh[ng][2], bh[ng][3]);
            }
#pragma unroll
            for (int ng = 0; ng < 4; ng++) {
                mma_bf16(accs[2 * ng],     ah, bl[ng][0], bl[ng][1]);
                mma_bf16(accs[2 * ng + 1], ah, bl[ng][2], bl[ng][3]);
            }
#pragma unroll
            for (int ng = 0; ng < 4; ng++) {
                mma_bf16(accs[2 * ng],     al, bh[ng][0], bh[ng][1]);
                mma_bf16(accs[2 * ng + 1], al, bh[ng][2], bh[ng][3]);
            }
        }

#pragma unroll
        for (int nt = 0; nt < 8; nt++) {
            int cb = k0 + nt * 8 + (lane & 3) * 2;
            accs[nt][0] = accs[nt][0] * scale + ((cb     > r0g) ? -1e9f : 0.0f);
            accs[nt][1] = accs[nt][1] * scale + ((cb + 1 > r0g) ? -1e9f : 0.0f);
            accs[nt][2] = accs[nt][2] * scale + ((cb     > r1g) ? -1e9f : 0.0f);
            accs[nt][3] = accs[nt][3] * scale + ((cb + 1 > r1g) ? -1e9f : 0.0f);
        }

        float mx0 = -1e30f, mx1 = -1e30f;
#pragma unroll
        for (int nt = 0; nt < 8; nt++) {
            mx0 = fmaxf(mx0, fmaxf(accs[nt][0], accs[nt][1]));
            mx1 = fmaxf(mx1, fmaxf(accs[nt][2], accs[nt][3]));
        }
        mx0 = fmaxf(mx0, __shfl_xor_sync(0xffffffffu, mx0, 1));
        mx0 = fmaxf(mx0, __shfl_xor_sync(0xffffffffu, mx0, 2));
        mx1 = fmaxf(mx1, __shfl_xor_sync(0xffffffffu, mx1, 1));
        mx1 = fmaxf(mx1, __shfl_xor_sync(0xffffffffu, mx1, 2));
        float mn0 = fmaxf(m0r, mx0), mn1 = fmaxf(m1r, mx1);
        float al0 = __expf(m0r - mn0), al1 = __expf(m1r - mn1);
        m0r = mn0; m1r = mn1;
        float rs0 = 0.0f, rs1 = 0.0f;
#pragma unroll
        for (int nt = 0; nt < 8; nt++) {
            accs[nt][0] = __expf(accs[nt][0] - mn0);
            accs[nt][1] = __expf(accs[nt][1] - mn0);
            accs[nt][2] = __expf(accs[nt][2] - mn1);
            accs[nt][3] = __expf(accs[nt][3] - mn1);
            rs0 += accs[nt][0] + accs[nt][1];
            rs1 += accs[nt][2] + accs[nt][3];
        }
        rs0 += __shfl_xor_sync(0xffffffffu, rs0, 1);
        rs0 += __shfl_xor_sync(0xffffffffu, rs0, 2);
        rs1 += __shfl_xor_sync(0xffffffffu, rs1, 1);
        rs1 += __shfl_xor_sync(0xffffffffu, rs1, 2);
        l0r = l0r * al0 + rs0;
        l1r = l1r * al1 + rs1;
#pragma unroll
        for (int i = 0; i < 16; i++) {
            acc_o[i][0] *= al0; acc_o[i][1] *= al0;
            acc_o[i][2] *= al1; acc_o[i][3] *= al1;
        }

        uint32_t ph[4][4], pl[4][4];
#pragma unroll
        for (int kk = 0; kk < 4; kk++) {
            int n0t = 2 * kk, n1t = 2 * kk + 1;
            ph[kk][0] = pack_hi(accs[n0t][0], accs[n0t][1]);
            pl[kk][0] = pack_lo(accs[n0t][0], accs[n0t][1], ph[kk][0]);
            ph[kk][1] = pack_hi(accs[n0t][2], accs[n0t][3]);
            pl[kk][1] = pack_lo(accs[n0t][2], accs[n0t][3], ph[kk][1]);
            ph[kk][2] = pack_hi(accs[n1t][0], accs[n1t][1]);
            pl[kk][2] = pack_lo(accs[n1t][0], accs[n1t][1], ph[kk][2]);
            ph[kk][3] = pack_hi(accs[n1t][2], accs[n1t][3]);
            pl[kk][3] = pack_lo(accs[n1t][2], accs[n1t][3], ph[kk][3]);
        }

#pragma unroll
        for (int kk = 0; kk < 4; kk++) {
#pragma unroll
            for (int gb = 0; gb < 8; gb += 4) {
                uint32_t vh[4][4], vl[4][4];
#pragma unroll
                for (int g = 0; g < 4; g++) {
                    ldm_x4(vh[g], vBaseH + (uint32_t)((gb + g) * 16 * FVS) * 2 + kk * 32);
                    ldm_x4(vl[g], vBaseL + (uint32_t)((gb + g) * 16 * FVS) * 2 + kk * 32);
                }
#pragma unroll
                for (int g = 0; g < 4; g++) {
                    mma_bf16(acc_o[2 * (gb + g)],     ph[kk], vh[g][0], vh[g][1]);
                    mma_bf16(acc_o[2 * (gb + g) + 1], ph[kk], vh[g][2], vh[g][3]);
                }
#pragma unroll
                for (int g = 0; g < 4; g++) {
                    mma_bf16(acc_o[2 * (gb + g)],     ph[kk], vl[g][0], vl[g][1]);
                    mma_bf16(acc_o[2 * (gb + g) + 1], ph[kk], vl[g][2], vl[g][3]);
                }
#pragma unroll
                for (int g = 0; g < 4; g++) {
                    mma_bf16(acc_o[2 * (gb + g)],     pl[kk], vh[g][0], vh[g][1]);
                    mma_bf16(acc_o[2 * (gb + g) + 1], pl[kk], vh[g][2], vh[g][3]);
                }
            }
        }
    }

    float inv0 = 1.0f / l0r, inv1 = 1.0f / l1r;
    size_t base0 = (size_t)(b * SQ + r0g) * HID + h * HD;
    size_t base1 = base0 + (size_t)8 * HID;
#pragma unroll
    for (int nto = 0; nto < 16; nto++) {
        int c = nto * 8 + (lane & 3) * 2;
        float v0 = acc_o[nto][0] * inv0, v1 = acc_o[nto][1] * inv0;
        uint32_t hw = pack_hi(v0, v1);
        *(uint32_t*)(g_Ah + base0 + c) = hw;
        *(uint32_t*)(g_Al + base0 + c) = pack_lo(v0, v1, hw);
        float v2 = acc_o[nto][2] * inv1, v3 = acc_o[nto][3] * inv1;
        hw = pack_hi(v2, v3);
        *(uint32_t*)(g_Ah + base1 + c) = hw;
        *(uint32_t*)(g_Al + base1 + c) = pack_lo(v2, v3, hw);
    }
}

/* ---------------- launcher ---------------------------------------------- */
extern "C" void kernel_launch(void* const* d_in, const int* in_sizes, int n_in,
                              void* d_out, int out_size) {
    (void)n_in; (void)out_size;
    const float* x   = (const float*)d_in[0];
    const float* cpq = (const float*)d_in[1];
    const float* cpk = (const float*)d_in[2];
    const float* cpv = (const float*)d_in[3];
    const float* cpo = (const float*)d_in[4];
    float* out = (float*)d_out;
    int ncp = in_sizes[1];

    __nv_bfloat16 *pWh, *pWl, *pXh, *pXl, *pAh, *pAl;
    float *pQ, *pK, *pV;
    cudaGetSymbolAddress((void**)&pWh, g_Wh);
    cudaGetSymbolAddress((void**)&pWl, g_Wl);
    cudaGetSymbolAddress((void**)&pXh, g_Xh);
    cudaGetSymbolAddress((void**)&pXl, g_Xl);
    cudaGetSymbolAddress((void**)&pAh, g_Ah);
    cudaGetSymbolAddress((void**)&pAl, g_Al);
    cudaGetSymbolAddress((void**)&pQ, g_Q);
    cudaGetSymbolAddress((void**)&pK, g_K);
    cudaGetSymbolAddress((void**)&pV, g_V);

    build_weights<<<(NW + 255) / 256, 256>>>(cpq, cpk, cpv, cpo, ncp);
    split_x<<<(MROWS * HID / 4 + 255) / 256, 256>>>(x);

    cudaFuncSetAttribute(gemm_hmma, cudaFuncAttributeMaxDynamicSharedMemorySize,
                         GEMM_SMEM);
    dim3 gg(HID / 128, MROWS / 128);
    gemm_hmma<<<gg, 512, GEMM_SMEM>>>(pXh, pXl, pWh + 0 * (size_t)NW, pWl + 0 * (size_t)NW, pQ);
    gemm_hmma<<<gg, 512, GEMM_SMEM>>>(pXh, pXl, pWh + 1 * (size_t)NW, pWl + 1 * (size_t)NW, pK);
    gemm_hmma<<<gg, 512, GEMM_SMEM>>>(pXh, pXl, pWh + 2 * (size_t)NW, pWl + 2 * (size_t)NW, pV);

    cudaFuncSetAttribute(flash_hmma, cudaFuncAttributeMaxDynamicSharedMemorySize,
                         FL_SMEM);
    flash_hmma<<<dim3(SQ / 128, NHEAD, NB), 256, FL_SMEM>>>(pQ, pK, pV);

    gemm_hmma<<<gg, 512, GEMM_SMEM>>>(pAh, pAl, pWh + 3 * (size_t)NW, pWl + 3 * (size_t)NW, out);
}

// round 11
// speedup vs baseline: 1.5215x; 1.5215x over previous
#include <cuda_runtime.h>
#include <cuda_fp16.h>
#include <math.h>
#include <stdint.h>

#define HID   2048
#define NB    2
#define SQ    2048
#define NHEAD 16
#define HD    128
#define MROWS (NB * SQ)        /* 4096 */
#define NW    (HID * HID)      /* 4194304 */
#define KDIM  2048

/* ---------------- scratch (device globals; no allocation allowed) -------- */
__device__ __half g_Wf[4][NW];          /* weights, single fp16             */
__device__ __half g_Xh[MROWS * HID];    /* activations hi                   */
__device__ __half g_Xl[MROWS * HID];    /* activations lo                   */
__device__ __half g_Ah[MROWS * HID];    /* attn output hi                   */
__device__ __half g_Al[MROWS * HID];    /* attn output lo                   */
__device__ float g_Q[MROWS * HID];
__device__ float g_K[MROWS * HID];
__device__ float g_V[MROWS * HID];

__device__ __forceinline__ uint32_t smem_u32(const void* p) {
    uint32_t a;
    asm("{ .reg .u64 t; cvta.to.shared.u64 t, %1; cvt.u32.u64 %0, t; }"
        : "=r"(a) : "l"(p));
    return a;
}
__device__ __forceinline__ void ldm_x4(uint32_t* r, uint32_t addr) {
    asm volatile("ldmatrix.sync.aligned.m8n8.x4.shared.b16 {%0,%1,%2,%3}, [%4];"
                 : "=r"(r[0]), "=r"(r[1]), "=r"(r[2]), "=r"(r[3]) : "r"(addr));
}
__device__ __forceinline__ void mma_f16(float* d, const uint32_t* a,
                                        uint32_t b0, uint32_t b1) {
    asm volatile("mma.sync.aligned.m16n8k16.row.col.f32.f16.f16.f32 "
                 "{%0,%1,%2,%3},{%4,%5,%6,%7},{%8,%9},{%0,%1,%2,%3};"
                 : "+f"(d[0]), "+f"(d[1]), "+f"(d[2]), "+f"(d[3])
                 : "r"(a[0]), "r"(a[1]), "r"(a[2]), "r"(a[3]), "r"(b0), "r"(b1));
}
__device__ __forceinline__ void split4h(float4 v, uint2& hi, uint2& lo) {
    __half2 h0 = __float22half2_rn(make_float2(v.x, v.y));
    __half2 h1 = __float22half2_rn(make_float2(v.z, v.w));
    float2 f0 = __half22float2(h0), f1 = __half22float2(h1);
    __half2 l0 = __float22half2_rn(make_float2(v.x - f0.x, v.y - f0.y));
    __half2 l1 = __float22half2_rn(make_float2(v.z - f1.x, v.w - f1.y));
    hi = make_uint2(*(uint32_t*)&h0, *(uint32_t*)&h1);
    lo = make_uint2(*(uint32_t*)&l0, *(uint32_t*)&l1);
}
__device__ __forceinline__ uint2 cvt4h(float4 v) {
    __half2 h0 = __float22half2_rn(make_float2(v.x, v.y));
    __half2 h1 = __float22half2_rn(make_float2(v.z, v.w));
    return make_uint2(*(uint32_t*)&h0, *(uint32_t*)&h1);
}
__device__ __forceinline__ uint32_t pack_h(float a, float b) {
    __half2 h = __float22half2_rn(make_float2(a, b));
    return *(uint32_t*)&h;
}
__device__ __forceinline__ uint32_t pack_hlo(float a, float b, uint32_t hi) {
    float2 f = __half22float2(*(__half2*)&hi);
    __half2 l = __float22half2_rn(make_float2(a - f.x, b - f.y));
    return *(uint32_t*)&l;
}
__device__ __forceinline__ void cp16(uint32_t smem, const void* g) {
    asm volatile("cp.async.cg.shared.global [%0], [%1], 16;"
                 :: "r"(smem), "l"(g) : "memory");
}
__device__ __forceinline__ void cp_commit() {
    asm volatile("cp.async.commit_group;" ::: "memory");
}
template <int N>
__device__ __forceinline__ void cp_wait() {
    asm volatile("cp.async.wait_group %0;" :: "n"(N) : "memory");
}

/* ---------------- weight reconstruction -> single fp16 ------------------- */
__global__ void build_weights(const float* __restrict__ cpq,
                              const float* __restrict__ cpk,
                              const float* __restrict__ cpv,
                              const float* __restrict__ cpo,
                              int ncp) {
    int i = blockIdx.x * 256 + threadIdx.x;
    if (i >= NW) return;
    const float dT = 1.0f / (float)(NW - 1);
    const float dX = 1.0f / (float)(ncp - 1);
    float t = (float)i * dT;
    int j = (int)((double)t * (double)(ncp - 1));
    if (j > ncp - 2) j = ncp - 2;
    if (j < 0) j = 0;
    while (j < ncp - 2 && (float)(j + 1) * dX <= t) j++;
    while (j > 0 && (float)j * dX > t) j--;
    float x0 = (float)j * dX;
    float x1 = (float)(j + 1) * dX;
    float f  = (t - x0) / (x1 - x0);
    const float* cps[4] = {cpq, cpk, cpv, cpo};
#pragma unroll
    for (int w = 0; w < 4; w++) {
        float a = cps[w][j];
        g_Wf[w][i] = __float2half_rn(fmaf(cps[w][j + 1] - a, f, a));
    }
}

/* ---------------- split hidden_states -> fp16 hi/lo ---------------------- */
__global__ void split_x(const float* __restrict__ x) {
    int i = blockIdx.x * 256 + threadIdx.x;
    if (i >= MROWS * HID / 4) return;
    float4 v = *(const float4*)(x + 4 * (size_t)i);
    uint2 hi, lo; split4h(v, hi, lo);
    *(uint2*)(g_Xh + 4 * (size_t)i) = hi;
    *(uint2*)(g_Xl + 4 * (size_t)i) = lo;
}

/* == fp16 2-term HMMA GEMM: C = (Ah+Al)*B^T.  CTA 128x128, 256 thr ======= */
#define KC      32
#define NCHUNK  (KDIM / KC)
#define SA      40                      /* halfwords per smem row (80 B)    */
#define OFF_AH  0
#define OFF_AL  (128 * SA)
#define OFF_B   (2 * 128 * SA)
#define STG_HW  (3 * 128 * SA)          /* 15360 halfwords                  */
#define STG_B   (STG_HW * 2)            /* 30720 B                          */
#define GEMM_SMEM (2 * STG_B)           /* 61440 B -> 2 CTAs/SM             */

__global__ void __launch_bounds__(256, 2) gemm_hmma(const __half* __restrict__ Ah,
                                                    const __half* __restrict__ Al,
                                                    const __half* __restrict__ B,
                                                    float* __restrict__ C) {
    extern __shared__ char shg[];
    const uint32_t sb = smem_u32(shg);
    const int tid = threadIdx.x;
    const int lane = tid & 31, wid = tid >> 5;
    const int warp_m = wid >> 2;              /* 0..1 : 64-row band         */
    const int warp_n = wid & 3;               /* 0..3 : 32-col band         */
    const int m0 = blockIdx.y * 128, n0 = blockIdx.x * 128;

    const int rA = tid >> 2;                  /* 0..63                      */
    const int cA = (tid & 3) << 3;            /* fp16 col 0,8,16,24         */
    const __half* gAh = Ah + (size_t)(m0 + rA) * KDIM + cA;
    const __half* gAl = Al + (size_t)(m0 + rA) * KDIM + cA;
    const __half* gB  = B  + (size_t)(n0 + rA) * KDIM + cA;
    const size_t rowskip = (size_t)64 * KDIM;
    const uint32_t d0 = sb + (uint32_t)(rA * SA + cA) * 2;
    const uint32_t d1 = d0 + (uint32_t)(64 * SA) * 2;

    float acc[4][4][4];
#pragma unroll
    for (int i = 0; i < 4; i++)
#pragma unroll
        for (int j = 0; j < 4; j++)
#pragma unroll
            for (int q = 0; q < 4; q++) acc[i][j][q] = 0.0f;

    const int rowA = lane & 15, colA8 = (lane >= 16) ? 8 : 0;
    const int rowB = (lane & 7) + ((lane >= 16) ? 8 : 0);
    const int colB8 = (lane & 8) ? 8 : 0;
    const uint32_t aoff = (uint32_t)((warp_m * 64 + rowA) * SA + colA8) * 2;
    const uint32_t boff = (uint32_t)((warp_n * 32 + rowB) * SA + colB8) * 2;

    /* prologue: chunk 0 -> stage 0 */
    {
        cp16(d0 + OFF_AH * 2, gAh);   cp16(d1 + OFF_AH * 2, gAh + rowskip);
        cp16(d0 + OFF_AL * 2, gAl);   cp16(d1 + OFF_AL * 2, gAl + rowskip);
        cp16(d0 + OFF_B  * 2, gB);    cp16(d1 + OFF_B  * 2, gB  + rowskip);
        cp_commit();
    }

    for (int c = 0; c < NCHUNK; c++) {
        cp_wait<0>();
        __syncthreads();
        if (c + 1 < NCHUNK) {
            const uint32_t st = ((c + 1) & 1) * STG_B;
            const int kc = (c + 1) * KC;
            cp16(d0 + st + OFF_AH * 2, gAh + kc);
            cp16(d1 + st + OFF_AH * 2, gAh + kc + rowskip);
            cp16(d0 + st + OFF_AL * 2, gAl + kc);
            cp16(d1 + st + OFF_AL * 2, gAl + kc + rowskip);
            cp16(d0 + st + OFF_B * 2,  gB + kc);
            cp16(d1 + st + OFF_B * 2,  gB + kc + rowskip);
            cp_commit();
        }

        const uint32_t stg = sb + (c & 1) * STG_B;
        const uint32_t tAh = stg + OFF_AH * 2, tAl = stg + OFF_AL * 2;
        const uint32_t tB  = stg + OFF_B * 2;
#pragma unroll
        for (int ks = 0; ks < 2; ks++) {
            const uint32_t ksoff = (uint32_t)(ks * 16) * 2;
            uint32_t ah[4][4], al[4][4];
#pragma unroll
            for (int mt = 0; mt < 4; mt++) {
                ldm_x4(ah[mt], tAh + aoff + ksoff + (uint32_t)(mt * 16 * SA) * 2);
                ldm_x4(al[mt], tAl + aoff + ksoff + (uint32_t)(mt * 16 * SA) * 2);
            }
#pragma unroll
            for (int g = 0; g < 2; g++) {
                uint32_t bb[4];
                ldm_x4(bb, tB + boff + ksoff + (uint32_t)(g * 16 * SA) * 2);
#pragma unroll
                for (int mt = 0; mt < 4; mt++) {
                    mma_f16(acc[mt][2 * g],     ah[mt], bb[0], bb[1]);
                    mma_f16(acc[mt][2 * g + 1], ah[mt], bb[2], bb[3]);
                }
#pragma unroll
                for (int mt = 0; mt < 4; mt++) {
                    mma_f16(acc[mt][2 * g],     al[mt], bb[0], bb[1]);
                    mma_f16(acc[mt][2 * g + 1], al[mt], bb[2], bb[3]);
                }
            }
        }
    }

    const int rowg = lane >> 2, colg = (lane & 3) * 2;
#pragma unroll
    for (int mt = 0; mt < 4; mt++) {
#pragma unroll
        for (int nt = 0; nt < 4; nt++) {
            int r = m0 + warp_m * 64 + mt * 16 + rowg;
            int cc = n0 + warp_n * 32 + nt * 8 + colg;
            *(float2*)(C + (size_t)r * KDIM + cc) =
                make_float2(acc[mt][nt][0], acc[mt][nt][1]);
            *(float2*)(C + (size_t)(r + 8) * KDIM + cc) =
                make_float2(acc[mt][nt][2], acc[mt][nt][3]);
        }
    }
}

/* ========== fp16 HMMA causal flash attention ============================= */
/* QK^T: Q split hi/lo (2 terms), K single. PV: P single, V single (1 term).*/
#define FKS 136
#define FVS 72
#define OFF_QH 0
#define OFF_QL (128 * FKS)
#define OFF_K  (2 * 128 * FKS)
#define OFF_VT (OFF_K + 64 * FKS)
#define FL_SMEM ((OFF_VT + 128 * FVS) * 2)

__global__ void __launch_bounds__(256, 1) flash_hmma(const float* __restrict__ Q,
                                                     const float* __restrict__ Km,
                                                     const float* __restrict__ Vm) {
    extern __shared__ char shf[];
    __half* s = (__half*)shf;
    const uint32_t sb = smem_u32(shf);
    const int tid = threadIdx.x, lane = tid & 31, wid = tid >> 5;
    const int qb = blockIdx.x, h = blockIdx.y, b = blockIdx.z;
    const int q0 = qb * 128;
    const int wm0 = wid * 16;
    const float scale = 0.08838834764831845f;

    const float* Qg = Q + (size_t)(b * SQ + q0) * HID + h * HD;
#pragma unroll
    for (int it = 0; it < 16; it++) {
        int idx = tid + it * 256;
        int r = idx >> 5, c4 = (idx & 31) << 2;
        float4 v = *(const float4*)(Qg + (size_t)r * HID + c4);
        uint2 hi, lo; split4h(v, hi, lo);
        *(uint2*)(s + OFF_QH + r * FKS + c4) = hi;
        *(uint2*)(s + OFF_QL + r * FKS + c4) = lo;
    }

    const uint32_t aBaseH = sb + 2u * (OFF_QH + (wm0 + (lane & 15)) * FKS + ((lane >> 4) << 3));
    const uint32_t aBaseL = sb + 2u * (OFF_QL + (wm0 + (lane & 15)) * FKS + ((lane >> 4) << 3));
    const int krow = (lane & 7) + ((lane >> 4) << 3);
    const uint32_t kBase = sb + 2u * (OFF_K + krow * FKS + (lane & 8));
    const uint32_t vBase = sb + 2u * (OFF_VT + krow * FVS + (lane & 8));

    float acc_o[16][4];
#pragma unroll
    for (int i = 0; i < 16; i++)
#pragma unroll
        for (int j = 0; j < 4; j++) acc_o[i][j] = 0.0f;
    float m0r = -1e30f, m1r = -1e30f, l0r = 0.0f, l1r = 0.0f;

    const int kb_max = 2 * qb + 1;
    const int r0g = q0 + wm0 + (lane >> 2);
    const int r1g = r0g + 8;

    for (int kb = 0; kb <= kb_max; kb++) {
        const int k0 = kb * 64;
        __syncthreads();
        const float* Kg = Km + (size_t)(b * SQ + k0) * HID + h * HD;
#pragma unroll
        for (int it = 0; it < 8; it++) {
            int idx = tid + it * 256;
            int r = idx >> 5, c4 = (idx & 31) << 2;
            float4 v = *(const float4*)(Kg + (size_t)r * HID + c4);
            *(uint2*)(s + OFF_K + r * FKS + c4) = cvt4h(v);
        }
        const float* Vg = Vm + (size_t)(b * SQ + k0) * HID + h * HD;
#pragma unroll
        for (int it = 0; it < 8; it++) {
            int idx = tid + it * 256;
            int r = idx & 63, c4 = (idx >> 6) << 2;
            float4 v = *(const float4*)(Vg + (size_t)r * HID + c4);
            float e[4] = {v.x, v.y, v.z, v.w};
#pragma unroll
            for (int q = 0; q < 4; q++)
                s[OFF_VT + (c4 + q) * FVS + r] = __float2half_rn(e[q]);
        }
        __syncthreads();

        if (k0 > q0 + wm0) continue;

        /* ---- S = Q K^T : 2 terms (Qh, Ql) x single K ---- */
        float accs[8][4];
#pragma unroll
        for (int i = 0; i < 8; i++)
#pragma unroll
            for (int j = 0; j < 4; j++) accs[i][j] = 0.0f;
#pragma unroll
        for (int ks = 0; ks < 8; ks++) {
            uint32_t qh[4], ql[4];
            ldm_x4(qh, aBaseH + ks * 32);
            ldm_x4(ql, aBaseL + ks * 32);
            uint32_t kk4[4][4];
#pragma unroll
            for (int ng = 0; ng < 4; ng++)
                ldm_x4(kk4[ng], kBase + (uint32_t)(ng * 16 * FKS) * 2 + ks * 32);
#pragma unroll
            for (int ng = 0; ng < 4; ng++) {
                mma_f16(accs[2 * ng],     qh, kk4[ng][0], kk4[ng][1]);
                mma_f16(accs[2 * ng + 1], qh, kk4[ng][2], kk4[ng][3]);
            }
#pragma unroll
            for (int ng = 0; ng < 4; ng++) {
                mma_f16(accs[2 * ng],     ql, kk4[ng][0], kk4[ng][1]);
                mma_f16(accs[2 * ng + 1], ql, kk4[ng][2], kk4[ng][3]);
            }
        }

#pragma unroll
        for (int nt = 0; nt < 8; nt++) {
            int cb = k0 + nt * 8 + (lane & 3) * 2;
            accs[nt][0] = accs[nt][0] * scale + ((cb     > r0g) ? -1e9f : 0.0f);
            accs[nt][1] = accs[nt][1] * scale + ((cb + 1 > r0g) ? -1e9f : 0.0f);
            accs[nt][2] = accs[nt][2] * scale + ((cb     > r1g) ? -1e9f : 0.0f);
            accs[nt][3] = accs[nt][3] * scale + ((cb + 1 > r1g) ? -1e9f : 0.0f);
        }

        float mx0 = -1e30f, mx1 = -1e30f;
#pragma unroll
        for (int nt = 0; nt < 8; nt++) {
            mx0 = fmaxf(mx0, fmaxf(accs[nt][0], accs[nt][1]));
            mx1 = fmaxf(mx1, fmaxf(accs[nt][2], accs[nt][3]));
        }
        mx0 = fmaxf(mx0, __shfl_xor_sync(0xffffffffu, mx0, 1));
        mx0 = fmaxf(mx0, __shfl_xor_sync(0xffffffffu, mx0, 2));
        mx1 = fmaxf(mx1, __shfl_xor_sync(0xffffffffu, mx1, 1));
        mx1 = fmaxf(mx1, __shfl_xor_sync(0xffffffffu, mx1, 2));
        float mn0 = fmaxf(m0r, mx0), mn1 = fmaxf(m1r, mx1);
        float al0 = __expf(m0r - mn0), al1 = __expf(m1r - mn1);
        m0r = mn0; m1r = mn1;
        float rs0 = 0.0f, rs1 = 0.0f;
#pragma unroll
        for (int nt = 0; nt < 8; nt++) {
            accs[nt][0] = __expf(accs[nt][0] - mn0);
            accs[nt][1] = __expf(accs[nt][1] - mn0);
            accs[nt][2] = __expf(accs[nt][2] - mn1);
            accs[nt][3] = __expf(accs[nt][3] - mn1);
            rs0 += accs[nt][0] + accs[nt][1];
            rs1 += accs[nt][2] + accs[nt][3];
        }
        rs0 += __shfl_xor_sync(0xffffffffu, rs0, 1);
        rs0 += __shfl_xor_sync(0xffffffffu, rs0, 2);
        rs1 += __shfl_xor_sync(0xffffffffu, rs1, 1);
        rs1 += __shfl_xor_sync(0xffffffffu, rs1, 2);
        l0r = l0r * al0 + rs0;
        l1r = l1r * al1 + rs1;
#pragma unroll
        for (int i = 0; i < 16; i++) {
            acc_o[i][0] *= al0; acc_o[i][1] *= al0;
            acc_o[i][2] *= al1; acc_o[i][3] *= al1;
        }

        /* ---- P fragments: single fp16 ---- */
        uint32_t ph[4][4];
#pragma unroll
        for (int kk = 0; kk < 4; kk++) {
            int n0t = 2 * kk, n1t = 2 * kk + 1;
            ph[kk][0] = pack_h(accs[n0t][0], accs[n0t][1]);
            ph[kk][1] = pack_h(accs[n0t][2], accs[n0t][3]);
            ph[kk][2] = pack_h(accs[n1t][0], accs[n1t][1]);
            ph[kk][3] = pack_h(accs[n1t][2], accs[n1t][3]);
        }

        /* ---- O += P V : single term ---- */
#pragma unroll
        for (int kk = 0; kk < 4; kk++) {
#pragma unroll
            for (int gb = 0; gb < 8; gb += 4) {
                uint32_t vt[4][4];
#pragma unroll
                for (int g = 0; g < 4; g++)
                    ldm_x4(vt[g], vBase + (uint32_t)((gb + g) * 16 * FVS) * 2 + kk * 32);
#pragma unroll
                for (int g = 0; g < 4; g++) {
                    mma_f16(acc_o[2 * (gb + g)],     ph[kk], vt[g][0], vt[g][1]);
                    mma_f16(acc_o[2 * (gb + g) + 1], ph[kk], vt[g][2], vt[g][3]);
                }
            }
        }
    }

    /* ---- epilogue: write attention output as fp16 hi/lo ---- */
    float inv0 = 1.0f / l0r, inv1 = 1.0f / l1r;
    size_t base0 = (size_t)(b * SQ + r0g) * HID + h * HD;
    size_t base1 = base0 + (size_t)8 * HID;
#pragma unroll
    for (int nto = 0; nto < 16; nto++) {
        int c = nto * 8 + (lane & 3) * 2;
        float v0 = acc_o[nto][0] * inv0, v1 = acc_o[nto][1] * inv0;
        uint32_t hw = pack_h(v0, v1);
        *(uint32_t*)(g_Ah + base0 + c) = hw;
        *(uint32_t*)(g_Al + base0 + c) = pack_hlo(v0, v1, hw);
        float v2 = acc_o[nto][2] * inv1, v3 = acc_o[nto][3] * inv1;
        hw = pack_h(v2, v3);
        *(uint32_t*)(g_Ah + base1 + c) = hw;
        *(uint32_t*)(g_Al + base1 + c) = pack_hlo(v2, v3, hw);
    }
}

/* ---------------- launcher ---------------------------------------------- */
extern "C" void kernel_launch(void* const* d_in, const int* in_sizes, int n_in,
                              void* d_out, int out_size) {
    (void)n_in; (void)out_size;
    const float* x   = (const float*)d_in[0];
    const float* cpq = (const float*)d_in[1];
    const float* cpk = (const float*)d_in[2];
    const float* cpv = (const float*)d_in[3];
    const float* cpo = (const float*)d_in[4];
    float* out = (float*)d_out;
    int ncp = in_sizes[1];

    __half *pWf, *pXh, *pXl, *pAh, *pAl;
    float *pQ, *pK, *pV;
    cudaGetSymbolAddress((void**)&pWf, g_Wf);
    cudaGetSymbolAddress((void**)&pXh, g_Xh);
    cudaGetSymbolAddress((void**)&pXl, g_Xl);
    cudaGetSymbolAddress((void**)&pAh, g_Ah);
    cudaGetSymbolAddress((void**)&pAl, g_Al);
    cudaGetSymbolAddress((void**)&pQ, g_Q);
    cudaGetSymbolAddress((void**)&pK, g_K);
    cudaGetSymbolAddress((void**)&pV, g_V);

    build_weights<<<(NW + 255) / 256, 256>>>(cpq, cpk, cpv, cpo, ncp);
    split_x<<<(MROWS * HID / 4 + 255) / 256, 256>>>(x);

    cudaFuncSetAttribute(gemm_hmma, cudaFuncAttributeMaxDynamicSharedMemorySize,
                         GEMM_SMEM);
    dim3 gg(HID / 128, MROWS / 128);
    gemm_hmma<<<gg, 256, GEMM_SMEM>>>(pXh, pXl, pWf + 0 * (size_t)NW, pQ);
    gemm_hmma<<<gg, 256, GEMM_SMEM>>>(pXh, pXl, pWf + 1 * (size_t)NW, pK);
    gemm_hmma<<<gg, 256, GEMM_SMEM>>>(pXh, pXl, pWf + 2 * (size_t)NW, pV);

    cudaFuncSetAttribute(flash_hmma, cudaFuncAttributeMaxDynamicSharedMemorySize,
                         FL_SMEM);
    flash_hmma<<<dim3(SQ / 128, NHEAD, NB), 256, FL_SMEM>>>(pQ, pK, pV);

    gemm_hmma<<<gg, 256, GEMM_SMEM>>>(pAh, pAl, pWf + 3 * (size_t)NW, out);
}

// round 12
// speedup vs baseline: 2.2282x; 1.4645x over previous
#include <cuda_runtime.h>
#include <cuda_fp16.h>
#include <math.h>
#include <stdint.h>

#define HID   2048
#define NB    2
#define SQ    2048
#define NHEAD 16
#define HD    128
#define MROWS (NB * SQ)        /* 4096 */
#define NW    (HID * HID)      /* 4194304 */
#define KDIM  2048

/* ---------------- scratch (device globals; no allocation allowed) -------- */
__device__ __half g_Wf[4][NW];          /* weights, single fp16             */
__device__ __half g_Xf[MROWS * HID];    /* activations, single fp16         */
__device__ __half g_Af[MROWS * HID];    /* attn output, single fp16         */
__device__ float g_Q[MROWS * HID];
__device__ float g_K[MROWS * HID];
__device__ float g_V[MROWS * HID];

__device__ __forceinline__ uint32_t smem_u32(const void* p) {
    uint32_t a;
    asm("{ .reg .u64 t; cvta.to.shared.u64 t, %1; cvt.u32.u64 %0, t; }"
        : "=r"(a) : "l"(p));
    return a;
}
__device__ __forceinline__ void ldm_x4(uint32_t* r, uint32_t addr) {
    asm volatile("ldmatrix.sync.aligned.m8n8.x4.shared.b16 {%0,%1,%2,%3}, [%4];"
                 : "=r"(r[0]), "=r"(r[1]), "=r"(r[2]), "=r"(r[3]) : "r"(addr));
}
__device__ __forceinline__ void mma_f16(float* d, const uint32_t* a,
                                        uint32_t b0, uint32_t b1) {
    asm volatile("mma.sync.aligned.m16n8k16.row.col.f32.f16.f16.f32 "
                 "{%0,%1,%2,%3},{%4,%5,%6,%7},{%8,%9},{%0,%1,%2,%3};"
                 : "+f"(d[0]), "+f"(d[1]), "+f"(d[2]), "+f"(d[3])
                 : "r"(a[0]), "r"(a[1]), "r"(a[2]), "r"(a[3]), "r"(b0), "r"(b1));
}
__device__ __forceinline__ void split4h(float4 v, uint2& hi, uint2& lo) {
    __half2 h0 = __float22half2_rn(make_float2(v.x, v.y));
    __half2 h1 = __float22half2_rn(make_float2(v.z, v.w));
    float2 f0 = __half22float2(h0), f1 = __half22float2(h1);
    __half2 l0 = __float22half2_rn(make_float2(v.x - f0.x, v.y - f0.y));
    __half2 l1 = __float22half2_rn(make_float2(v.z - f1.x, v.w - f1.y));
    hi = make_uint2(*(uint32_t*)&h0, *(uint32_t*)&h1);
    lo = make_uint2(*(uint32_t*)&l0, *(uint32_t*)&l1);
}
__device__ __forceinline__ uint2 cvt4h(float4 v) {
    __half2 h0 = __float22half2_rn(make_float2(v.x, v.y));
    __half2 h1 = __float22half2_rn(make_float2(v.z, v.w));
    return make_uint2(*(uint32_t*)&h0, *(uint32_t*)&h1);
}
__device__ __forceinline__ uint32_t pack_h(float a, float b) {
    __half2 h = __float22half2_rn(make_float2(a, b));
    return *(uint32_t*)&h;
}
__device__ __forceinline__ void cp16(uint32_t smem, const void* g) {
    asm volatile("cp.async.cg.shared.global [%0], [%1], 16;"
                 :: "r"(smem), "l"(g) : "memory");
}
__device__ __forceinline__ void cp_commit() {
    asm volatile("cp.async.commit_group;" ::: "memory");
}
template <int N>
__device__ __forceinline__ void cp_wait() {
    asm volatile("cp.async.wait_group %0;" :: "n"(N) : "memory");
}

/* ---------------- weight reconstruction -> single fp16 ------------------- */
__global__ void build_weights(const float* __restrict__ cpq,
                              const float* __restrict__ cpk,
                              const float* __restrict__ cpv,
                              const float* __restrict__ cpo,
                              int ncp) {
    int i = blockIdx.x * 256 + threadIdx.x;
    if (i >= NW) return;
    const float dT = 1.0f / (float)(NW - 1);
    const float dX = 1.0f / (float)(ncp - 1);
    float t = (float)i * dT;
    int j = (int)((double)t * (double)(ncp - 1));
    if (j > ncp - 2) j = ncp - 2;
    if (j < 0) j = 0;
    while (j < ncp - 2 && (float)(j + 1) * dX <= t) j++;
    while (j > 0 && (float)j * dX > t) j--;
    float x0 = (float)j * dX;
    float x1 = (float)(j + 1) * dX;
    float f  = (t - x0) / (x1 - x0);
    const float* cps[4] = {cpq, cpk, cpv, cpo};
#pragma unroll
    for (int w = 0; w < 4; w++) {
        float a = cps[w][j];
        g_Wf[w][i] = __float2half_rn(fmaf(cps[w][j + 1] - a, f, a));
    }
}

/* ---------------- convert hidden_states -> single fp16 ------------------- */
__global__ void split_x(const float* __restrict__ x) {
    int i = blockIdx.x * 256 + threadIdx.x;
    if (i >= MROWS * HID / 4) return;
    float4 v = *(const float4*)(x + 4 * (size_t)i);
    *(uint2*)(g_Xf + 4 * (size_t)i) = cvt4h(v);
}

/* == fp16 single-term HMMA GEMM: C = A*B^T.  CTA 128x128, 256 thr ======== */
#define KC      32
#define NCHUNK  (KDIM / KC)
#define SA      40                      /* halfwords per smem row (80 B)    */
#define OFF_A   0
#define OFF_B   (128 * SA)
#define STG_HW  (2 * 128 * SA)          /* 10240 halfwords                  */
#define STG_B   (STG_HW * 2)            /* 20480 B                          */
#define GEMM_SMEM (2 * STG_B)           /* 40960 B                          */

__global__ void __launch_bounds__(256, 2) gemm_hmma(const __half* __restrict__ A,
                                                    const __half* __restrict__ B,
                                                    float* __restrict__ C) {
    extern __shared__ char shg[];
    const uint32_t sb = smem_u32(shg);
    const int tid = threadIdx.x;
    const int lane = tid & 31, wid = tid >> 5;
    const int warp_m = wid >> 2;              /* 0..1 : 64-row band         */
    const int warp_n = wid & 3;               /* 0..3 : 32-col band         */
    const int m0 = blockIdx.y * 128, n0 = blockIdx.x * 128;

    const int rA = tid >> 2;                  /* 0..63                      */
    const int cA = (tid & 3) << 3;            /* fp16 col 0,8,16,24         */
    const __half* gA = A + (size_t)(m0 + rA) * KDIM + cA;
    const __half* gB = B + (size_t)(n0 + rA) * KDIM + cA;
    const size_t rowskip = (size_t)64 * KDIM;
    const uint32_t d0 = sb + (uint32_t)(rA * SA + cA) * 2;
    const uint32_t d1 = d0 + (uint32_t)(64 * SA) * 2;

    float acc[4][4][4];
#pragma unroll
    for (int i = 0; i < 4; i++)
#pragma unroll
        for (int j = 0; j < 4; j++)
#pragma unroll
            for (int q = 0; q < 4; q++) acc[i][j][q] = 0.0f;

    const int rowA = lane & 15, colA8 = (lane >= 16) ? 8 : 0;
    const int rowB = (lane & 7) + ((lane >= 16) ? 8 : 0);
    const int colB8 = (lane & 8) ? 8 : 0;
    const uint32_t aoff = (uint32_t)((warp_m * 64 + rowA) * SA + colA8) * 2;
    const uint32_t boff = (uint32_t)((warp_n * 32 + rowB) * SA + colB8) * 2;

    /* prologue: chunk 0 -> stage 0 */
    {
        cp16(d0 + OFF_A * 2, gA);   cp16(d1 + OFF_A * 2, gA + rowskip);
        cp16(d0 + OFF_B * 2, gB);   cp16(d1 + OFF_B * 2, gB + rowskip);
        cp_commit();
    }

    for (int c = 0; c < NCHUNK; c++) {
        cp_wait<0>();
        __syncthreads();
        if (c + 1 < NCHUNK) {
            const uint32_t st = ((c + 1) & 1) * STG_B;
            const int kc = (c + 1) * KC;
            cp16(d0 + st + OFF_A * 2, gA + kc);
            cp16(d1 + st + OFF_A * 2, gA + kc + rowskip);
            cp16(d0 + st + OFF_B * 2, gB + kc);
            cp16(d1 + st + OFF_B * 2, gB + kc + rowskip);
            cp_commit();
        }

        const uint32_t stg = sb + (c & 1) * STG_B;
        const uint32_t tA = stg + OFF_A * 2, tB = stg + OFF_B * 2;
#pragma unroll
        for (int ks = 0; ks < 2; ks++) {
            const uint32_t ksoff = (uint32_t)(ks * 16) * 2;
            uint32_t ah[4][4];
#pragma unroll
            for (int mt = 0; mt < 4; mt++)
                ldm_x4(ah[mt], tA + aoff + ksoff + (uint32_t)(mt * 16 * SA) * 2);
#pragma unroll
            for (int g = 0; g < 2; g++) {
                uint32_t bb[4];
                ldm_x4(bb, tB + boff + ksoff + (uint32_t)(g * 16 * SA) * 2);
#pragma unroll
                for (int mt = 0; mt < 4; mt++) {
                    mma_f16(acc[mt][2 * g],     ah[mt], bb[0], bb[1]);
                    mma_f16(acc[mt][2 * g + 1], ah[mt], bb[2], bb[3]);
                }
            }
        }
    }

    const int rowg = lane >> 2, colg = (lane & 3) * 2;
#pragma unroll
    for (int mt = 0; mt < 4; mt++) {
#pragma unroll
        for (int nt = 0; nt < 4; nt++) {
            int r = m0 + warp_m * 64 + mt * 16 + rowg;
            int cc = n0 + warp_n * 32 + nt * 8 + colg;
            *(float2*)(C + (size_t)r * KDIM + cc) =
                make_float2(acc[mt][nt][0], acc[mt][nt][1]);
            *(float2*)(C + (size_t)(r + 8) * KDIM + cc) =
                make_float2(acc[mt][nt][2], acc[mt][nt][3]);
        }
    }
}

/* ========== fp16 HMMA causal flash attention ============================= */
/* QK^T: Q split hi/lo (2 terms), K single. PV: P single, V single.         */
#define FKS 136
#define FVS 72
#define OFF_QH 0
#define OFF_QL (128 * FKS)
#define OFF_K  (2 * 128 * FKS)
#define OFF_VT (OFF_K + 64 * FKS)
#define FL_SMEM ((OFF_VT + 128 * FVS) * 2)

__global__ void __launch_bounds__(256, 1) flash_hmma(const float* __restrict__ Q,
                                                     const float* __restrict__ Km,
                                                     const float* __restrict__ Vm) {
    extern __shared__ char shf[];
    __half* s = (__half*)shf;
    const uint32_t sb = smem_u32(shf);
    const int tid = threadIdx.x, lane = tid & 31, wid = tid >> 5;
    /* heavy (high-qb) tiles first for better backfill */
    const int qb = (int)gridDim.x - 1 - (int)blockIdx.x;
    const int h = blockIdx.y, b = blockIdx.z;
    const int q0 = qb * 128;
    const int wm0 = wid * 16;
    const float scale = 0.08838834764831845f;

    const float* Qg = Q + (size_t)(b * SQ + q0) * HID + h * HD;
#pragma unroll
    for (int it = 0; it < 16; it++) {
        int idx = tid + it * 256;
        int r = idx >> 5, c4 = (idx & 31) << 2;
        float4 v = *(const float4*)(Qg + (size_t)r * HID + c4);
        uint2 hi, lo; split4h(v, hi, lo);
        *(uint2*)(s + OFF_QH + r * FKS + c4) = hi;
        *(uint2*)(s + OFF_QL + r * FKS + c4) = lo;
    }

    const uint32_t aBaseH = sb + 2u * (OFF_QH + (wm0 + (lane & 15)) * FKS + ((lane >> 4) << 3));
    const uint32_t aBaseL = sb + 2u * (OFF_QL + (wm0 + (lane & 15)) * FKS + ((lane >> 4) << 3));
    const int krow = (lane & 7) + ((lane >> 4) << 3);
    const uint32_t kBase = sb + 2u * (OFF_K + krow * FKS + (lane & 8));
    const uint32_t vBase = sb + 2u * (OFF_VT + krow * FVS + (lane & 8));

    float acc_o[16][4];
#pragma unroll
    for (int i = 0; i < 16; i++)
#pragma unroll
        for (int j = 0; j < 4; j++) acc_o[i][j] = 0.0f;
    float m0r = -1e30f, m1r = -1e30f, l0r = 0.0f, l1r = 0.0f;

    const int kb_max = 2 * qb + 1;
    const int r0g = q0 + wm0 + (lane >> 2);
    const int r1g = r0g + 8;

    for (int kb = 0; kb <= kb_max; kb++) {
        const int k0 = kb * 64;
        __syncthreads();
        const float* Kg = Km + (size_t)(b * SQ + k0) * HID + h * HD;
#pragma unroll
        for (int it = 0; it < 8; it++) {
            int idx = tid + it * 256;
            int r = idx >> 5, c4 = (idx & 31) << 2;
            float4 v = *(const float4*)(Kg + (size_t)r * HID + c4);
            *(uint2*)(s + OFF_K + r * FKS + c4) = cvt4h(v);
        }
        const float* Vg = Vm + (size_t)(b * SQ + k0) * HID + h * HD;
#pragma unroll
        for (int it = 0; it < 8; it++) {
            int idx = tid + it * 256;
            int r = idx & 63, c4 = (idx >> 6) << 2;
            float4 v = *(const float4*)(Vg + (size_t)r * HID + c4);
            float e[4] = {v.x, v.y, v.z, v.w};
#pragma unroll
            for (int q = 0; q < 4; q++)
                s[OFF_VT + (c4 + q) * FVS + r] = __float2half_rn(e[q]);
        }
        __syncthreads();

        if (k0 > q0 + wm0) continue;

        float accs[8][4];
#pragma unroll
        for (int i = 0; i < 8; i++)
#pragma unroll
            for (int j = 0; j < 4; j++) accs[i][j] = 0.0f;
#pragma unroll
        for (int ks = 0; ks < 8; ks++) {
            uint32_t qh[4], ql[4];
            ldm_x4(qh, aBaseH + ks * 32);
            ldm_x4(ql, aBaseL + ks * 32);
            uint32_t kk4[4][4];
#pragma unroll
            for (int ng = 0; ng < 4; ng++)
                ldm_x4(kk4[ng], kBase + (uint32_t)(ng * 16 * FKS) * 2 + ks * 32);
#pragma unroll
            for (int ng = 0; ng < 4; ng++) {
                mma_f16(accs[2 * ng],     qh, kk4[ng][0], kk4[ng][1]);
                mma_f16(accs[2 * ng + 1], qh, kk4[ng][2], kk4[ng][3]);
            }
#pragma unroll
            for (int ng = 0; ng < 4; ng++) {
                mma_f16(accs[2 * ng],     ql, kk4[ng][0], kk4[ng][1]);
                mma_f16(accs[2 * ng + 1], ql, kk4[ng][2], kk4[ng][3]);
            }
        }

#pragma unroll
        for (int nt = 0; nt < 8; nt++) {
            int cb = k0 + nt * 8 + (lane & 3) * 2;
            accs[nt][0] = accs[nt][0] * scale + ((cb     > r0g) ? -1e9f : 0.0f);
            accs[nt][1] = accs[nt][1] * scale + ((cb + 1 > r0g) ? -1e9f : 0.0f);
            accs[nt][2] = accs[nt][2] * scale + ((cb     > r1g) ? -1e9f : 0.0f);
            accs[nt][3] = accs[nt][3] * scale + ((cb + 1 > r1g) ? -1e9f : 0.0f);
        }

        float mx0 = -1e30f, mx1 = -1e30f;
#pragma unroll
        for (int nt = 0; nt < 8; nt++) {
            mx0 = fmaxf(mx0, fmaxf(accs[nt][0], accs[nt][1]));
            mx1 = fmaxf(mx1, fmaxf(accs[nt][2], accs[nt][3]));
        }
        mx0 = fmaxf(mx0, __shfl_xor_sync(0xffffffffu, mx0, 1));
        mx0 = fmaxf(mx0, __shfl_xor_sync(0xffffffffu, mx0, 2));
        mx1 = fmaxf(mx1, __shfl_xor_sync(0xffffffffu, mx1, 1));
        mx1 = fmaxf(mx1, __shfl_xor_sync(0xffffffffu, mx1, 2));
        float mn0 = fmaxf(m0r, mx0), mn1 = fmaxf(m1r, mx1);
        float al0 = __expf(m0r - mn0), al1 = __expf(m1r - mn1);
        m0r = mn0; m1r = mn1;
        float rs0 = 0.0f, rs1 = 0.0f;
#pragma unroll
        for (int nt = 0; nt < 8; nt++) {
            accs[nt][0] = __expf(accs[nt][0] - mn0);
            accs[nt][1] = __expf(accs[nt][1] - mn0);
            accs[nt][2] = __expf(accs[nt][2] - mn1);
            accs[nt][3] = __expf(accs[nt][3] - mn1);
            rs0 += accs[nt][0] + accs[nt][1];
            rs1 += accs[nt][2] + accs[nt][3];
        }
        rs0 += __shfl_xor_sync(0xffffffffu, rs0, 1);
        rs0 += __shfl_xor_sync(0xffffffffu, rs0, 2);
        rs1 += __shfl_xor_sync(0xffffffffu, rs1, 1);
        rs1 += __shfl_xor_sync(0xffffffffu, rs1, 2);
        l0r = l0r * al0 + rs0;
        l1r = l1r * al1 + rs1;
#pragma unroll
        for (int i = 0; i < 16; i++) {
            acc_o[i][0] *= al0; acc_o[i][1] *= al0;
            acc_o[i][2] *= al1; acc_o[i][3] *= al1;
        }

        uint32_t ph[4][4];
#pragma unroll
        for (int kk = 0; kk < 4; kk++) {
            int n0t = 2 * kk, n1t = 2 * kk + 1;
            ph[kk][0] = pack_h(accs[n0t][0], accs[n0t][1]);
            ph[kk][1] = pack_h(accs[n0t][2], accs[n0t][3]);
            ph[kk][2] = pack_h(accs[n1t][0], accs[n1t][1]);
            ph[kk][3] = pack_h(accs[n1t][2], accs[n1t][3]);
        }

#pragma unroll
        for (int kk = 0; kk < 4; kk++) {
#pragma unroll
            for (int gb = 0; gb < 8; gb += 4) {
                uint32_t vt[4][4];
#pragma unroll
                for (int g = 0; g < 4; g++)
                    ldm_x4(vt[g], vBase + (uint32_t)((gb + g) * 16 * FVS) * 2 + kk * 32);
#pragma unroll
                for (int g = 0; g < 4; g++) {
                    mma_f16(acc_o[2 * (gb + g)],     ph[kk], vt[g][0], vt[g][1]);
                    mma_f16(acc_o[2 * (gb + g) + 1], ph[kk], vt[g][2], vt[g][3]);
                }
            }
        }
    }

    /* ---- epilogue: attention output as single fp16 ---- */
    float inv0 = 1.0f / l0r, inv1 = 1.0f / l1r;
    size_t base0 = (size_t)(b * SQ + r0g) * HID + h * HD;
    size_t base1 = base0 + (size_t)8 * HID;
#pragma unroll
    for (int nto = 0; nto < 16; nto++) {
        int c = nto * 8 + (lane & 3) * 2;
        *(uint32_t*)(g_Af + base0 + c) = pack_h(acc_o[nto][0] * inv0, acc_o[nto][1] * inv0);
        *(uint32_t*)(g_Af + base1 + c) = pack_h(acc_o[nto][2] * inv1, acc_o[nto][3] * inv1);
    }
}

/* ---------------- launcher ---------------------------------------------- */
extern "C" void kernel_launch(void* const* d_in, const int* in_sizes, int n_in,
                              void* d_out, int out_size) {
    (void)n_in; (void)out_size;
    const float* x   = (const float*)d_in[0];
    const float* cpq = (const float*)d_in[1];
    const float* cpk = (const float*)d_in[2];
    const float* cpv = (const float*)d_in[3];
    const float* cpo = (const float*)d_in[4];
    float* out = (float*)d_out;
    int ncp = in_sizes[1];

    __half *pWf, *pXf, *pAf;
    float *pQ, *pK, *pV;
    cudaGetSymbolAddress((void**)&pWf, g_Wf);
    cudaGetSymbolAddress((void**)&pXf, g_Xf);
    cudaGetSymbolAddress((void**)&pAf, g_Af);
    cudaGetSymbolAddress((void**)&pQ, g_Q);
    cudaGetSymbolAddress((void**)&pK, g_K);
    cudaGetSymbolAddress((void**)&pV, g_V);

    build_weights<<<(NW + 255) / 256, 256>>>(cpq, cpk, cpv, cpo, ncp);
    split_x<<<(MROWS * HID / 4 + 255) / 256, 256>>>(x);

    cudaFuncSetAttribute(gemm_hmma, cudaFuncAttributeMaxDynamicSharedMemorySize,
                         GEMM_SMEM);
    dim3 gg(HID / 128, MROWS / 128);
    gemm_hmma<<<gg, 256, GEMM_SMEM>>>(pXf, pWf + 0 * (size_t)NW, pQ);
    gemm_hmma<<<gg, 256, GEMM_SMEM>>>(pXf, pWf + 1 * (size_t)NW, pK);
    gemm_hmma<<<gg, 256, GEMM_SMEM>>>(pXf, pWf + 2 * (size_t)NW, pV);

    cudaFuncSetAttribute(flash_hmma, cudaFuncAttributeMaxDynamicSharedMemorySize,
                         FL_SMEM);
    flash_hmma<<<dim3(SQ / 128, NHEAD, NB), 256, FL_SMEM>>>(pQ, pK, pV);

    gemm_hmma<<<gg, 256, GEMM_SMEM>>>(pAf, pWf + 3 * (size_t)NW, out);
}

// round 13
// speedup vs baseline: 2.5680x; 1.1525x over previous
#include <cuda_runtime.h>
#include <cuda_fp16.h>
#include <math.h>
#include <stdint.h>

#define HID   2048
#define NB    2
#define SQ    2048
#define NHEAD 16
#define HD    128
#define MROWS (NB * SQ)        /* 4096 */
#define NW    (HID * HID)      /* 4194304 */
#define KDIM  2048

/* ---------------- scratch (device globals; no allocation allowed) -------- */
__device__ __half g_Wf[4][NW];          /* weights, single fp16             */
__device__ __half g_Xf[MROWS * HID];    /* activations, single fp16         */
__device__ __half g_Af[MROWS * HID];    /* attn output, single fp16         */
__device__ float g_Q[MROWS * HID];
__device__ float g_K[MROWS * HID];
__device__ float g_V[MROWS * HID];
__device__ __half g_QH[MROWS * HID];    /* Q hi fp16                        */
__device__ __half g_QL[MROWS * HID];    /* Q lo fp16                        */
__device__ __half g_Kf[MROWS * HID];    /* K fp16                           */
__device__ __half g_VT[MROWS * HID];    /* V fp16, transposed [b,h,d,s]     */

__device__ __forceinline__ uint32_t smem_u32(const void* p) {
    uint32_t a;
    asm("{ .reg .u64 t; cvta.to.shared.u64 t, %1; cvt.u32.u64 %0, t; }"
        : "=r"(a) : "l"(p));
    return a;
}
__device__ __forceinline__ void ldm_x4(uint32_t* r, uint32_t addr) {
    asm volatile("ldmatrix.sync.aligned.m8n8.x4.shared.b16 {%0,%1,%2,%3}, [%4];"
                 : "=r"(r[0]), "=r"(r[1]), "=r"(r[2]), "=r"(r[3]) : "r"(addr));
}
__device__ __forceinline__ void mma_f16(float* d, const uint32_t* a,
                                        uint32_t b0, uint32_t b1) {
    asm volatile("mma.sync.aligned.m16n8k16.row.col.f32.f16.f16.f32 "
                 "{%0,%1,%2,%3},{%4,%5,%6,%7},{%8,%9},{%0,%1,%2,%3};"
                 : "+f"(d[0]), "+f"(d[1]), "+f"(d[2]), "+f"(d[3])
                 : "r"(a[0]), "r"(a[1]), "r"(a[2]), "r"(a[3]), "r"(b0), "r"(b1));
}
__device__ __forceinline__ void split4h(float4 v, uint2& hi, uint2& lo) {
    __half2 h0 = __float22half2_rn(make_float2(v.x, v.y));
    __half2 h1 = __float22half2_rn(make_float2(v.z, v.w));
    float2 f0 = __half22float2(h0), f1 = __half22float2(h1);
    __half2 l0 = __float22half2_rn(make_float2(v.x - f0.x, v.y - f0.y));
    __half2 l1 = __float22half2_rn(make_float2(v.z - f1.x, v.w - f1.y));
    hi = make_uint2(*(uint32_t*)&h0, *(uint32_t*)&h1);
    lo = make_uint2(*(uint32_t*)&l0, *(uint32_t*)&l1);
}
__device__ __forceinline__ uint2 cvt4h(float4 v) {
    __half2 h0 = __float22half2_rn(make_float2(v.x, v.y));
    __half2 h1 = __float22half2_rn(make_float2(v.z, v.w));
    return make_uint2(*(uint32_t*)&h0, *(uint32_t*)&h1);
}
__device__ __forceinline__ uint32_t pack_h(float a, float b) {
    __half2 h = __float22half2_rn(make_float2(a, b));
    return *(uint32_t*)&h;
}
__device__ __forceinline__ void cp16(uint32_t smem, const void* g) {
    asm volatile("cp.async.cg.shared.global [%0], [%1], 16;"
                 :: "r"(smem), "l"(g) : "memory");
}
__device__ __forceinline__ void cp_commit() {
    asm volatile("cp.async.commit_group;" ::: "memory");
}
template <int N>
__device__ __forceinline__ void cp_wait() {
    asm volatile("cp.async.wait_group %0;" :: "n"(N) : "memory");
}

/* ---------------- weight reconstruction -> single fp16 ------------------- */
__global__ void build_weights(const float* __restrict__ cpq,
                              const float* __restrict__ cpk,
                              const float* __restrict__ cpv,
                              const float* __restrict__ cpo,
                              int ncp) {
    int i = blockIdx.x * 256 + threadIdx.x;
    if (i >= NW) return;
    const float dT = 1.0f / (float)(NW - 1);
    const float dX = 1.0f / (float)(ncp - 1);
    float t = (float)i * dT;
    int j = (int)((double)t * (double)(ncp - 1));
    if (j > ncp - 2) j = ncp - 2;
    if (j < 0) j = 0;
    while (j < ncp - 2 && (float)(j + 1) * dX <= t) j++;
    while (j > 0 && (float)j * dX > t) j--;
    float x0 = (float)j * dX;
    float x1 = (float)(j + 1) * dX;
    float f  = (t - x0) / (x1 - x0);
    const float* cps[4] = {cpq, cpk, cpv, cpo};
#pragma unroll
    for (int w = 0; w < 4; w++) {
        float a = cps[w][j];
        g_Wf[w][i] = __float2half_rn(fmaf(cps[w][j + 1] - a, f, a));
    }
}

/* ---------------- convert hidden_states -> single fp16 ------------------- */
__global__ void split_x(const float* __restrict__ x) {
    int i = blockIdx.x * 256 + threadIdx.x;
    if (i >= MROWS * HID / 4) return;
    float4 v = *(const float4*)(x + 4 * (size_t)i);
    *(uint2*)(g_Xf + 4 * (size_t)i) = cvt4h(v);
}

/* ---------------- Q -> hi/lo fp16, K -> fp16 (elementwise) --------------- */
__global__ void cvt_qk(const float* __restrict__ Q, const float* __restrict__ K) {
    int i = blockIdx.x * 256 + threadIdx.x;
    if (i >= MROWS * HID / 4) return;
    float4 q = *(const float4*)(Q + 4 * (size_t)i);
    uint2 hi, lo; split4h(q, hi, lo);
    *(uint2*)(g_QH + 4 * (size_t)i) = hi;
    *(uint2*)(g_QL + 4 * (size_t)i) = lo;
    float4 k = *(const float4*)(K + 4 * (size_t)i);
    *(uint2*)(g_Kf + 4 * (size_t)i) = cvt4h(k);
}

/* ---------------- V fp32 [b,s,h,d] -> VT fp16 [b,h,d,s] ------------------ */
__global__ void vtrans(const float* __restrict__ V) {
    __shared__ __half t[32][33];
    const int tx = threadIdx.x, ty = threadIdx.y;      /* 32 x 8 */
    const int s0 = blockIdx.x * 32, d0 = blockIdx.y * 32;
    const int bh = blockIdx.z;                          /* b*16 + h */
    const int b = bh >> 4, h = bh & 15;
#pragma unroll
    for (int k = 0; k < 4; k++) {
        int srow = s0 + ty + 8 * k;
        t[ty + 8 * k][tx] =
            __float2half_rn(V[(size_t)(b * SQ + srow) * HID + h * HD + d0 + tx]);
    }
    __syncthreads();
#pragma unroll
    for (int k = 0; k < 4; k++) {
        int drow = d0 + ty + 8 * k;
        g_VT[(size_t)(bh * HD + drow) * SQ + s0 + tx] = t[tx][ty + 8 * k];
    }
}

/* == fp16 HMMA GEMM: C = A*B^T.  CTA 128x128, 256 thr, KC=64 ============= */
#define KC      64
#define NCHUNK  (KDIM / KC)
#define SA      72                      /* halfwords per smem row (144 B)   */
#define OFF_A   0
#define OFF_B   (128 * SA)
#define STG_HW  (2 * 128 * SA)          /* 18432 halfwords                  */
#define STG_B   (STG_HW * 2)            /* 36864 B                          */
#define GEMM_SMEM (2 * STG_B)           /* 73728 B                          */

__global__ void __launch_bounds__(256, 2) gemm_hmma(const __half* __restrict__ A,
                                                    const __half* __restrict__ B,
                                                    float* __restrict__ C) {
    extern __shared__ char shg[];
    const uint32_t sb = smem_u32(shg);
    const int tid = threadIdx.x;
    const int lane = tid & 31, wid = tid >> 5;
    const int warp_m = wid >> 2;              /* 0..1 : 64-row band         */
    const int warp_n = wid & 3;               /* 0..3 : 32-col band         */
    const int m0 = blockIdx.y * 128, n0 = blockIdx.x * 128;

    /* cp.async coords: 8 threads per 128B row, 32 rows per pass, 4 passes */
    const int rL = tid >> 3;                  /* 0..31                      */
    const int cL = (tid & 7) << 3;            /* halfword col 0..56         */
    const __half* gA = A + (size_t)(m0 + rL) * KDIM + cL;
    const __half* gB = B + (size_t)(n0 + rL) * KDIM + cL;
    uint32_t dA[4], dB[4];
#pragma unroll
    for (int p = 0; p < 4; p++) {
        dA[p] = sb + (uint32_t)((rL + 32 * p) * SA + cL) * 2;
        dB[p] = dA[p] + (uint32_t)OFF_B * 2;
    }

    float acc[4][4][4];
#pragma unroll
    for (int i = 0; i < 4; i++)
#pragma unroll
        for (int j = 0; j < 4; j++)
#pragma unroll
            for (int q = 0; q < 4; q++) acc[i][j][q] = 0.0f;

    const int rowA = lane & 15, colA8 = (lane >= 16) ? 8 : 0;
    const int rowB = (lane & 7) + ((lane >= 16) ? 8 : 0);
    const int colB8 = (lane & 8) ? 8 : 0;
    const uint32_t aoff = (uint32_t)((warp_m * 64 + rowA) * SA + colA8) * 2;
    const uint32_t boff = (uint32_t)((warp_n * 32 + rowB) * SA + colB8) * 2;

    /* prologue: chunk 0 -> stage 0 */
    {
#pragma unroll
        for (int p = 0; p < 4; p++) {
            cp16(dA[p], gA + (size_t)(32 * p) * KDIM);
            cp16(dB[p], gB + (size_t)(32 * p) * KDIM);
        }
        cp_commit();
    }

    for (int c = 0; c < NCHUNK; c++) {
        cp_wait<0>();
        __syncthreads();
        if (c + 1 < NCHUNK) {
            const uint32_t st = ((c + 1) & 1) * STG_B;
            const int kc = (c + 1) * KC;
#pragma unroll
            for (int p = 0; p < 4; p++) {
                cp16(dA[p] + st, gA + (size_t)(32 * p) * KDIM + kc);
                cp16(dB[p] + st, gB + (size_t)(32 * p) * KDIM + kc);
            }
            cp_commit();
        }

        const uint32_t stg = sb + (c & 1) * STG_B;
        const uint32_t tA = stg + OFF_A * 2, tB = stg + OFF_B * 2;
#pragma unroll
        for (int ks = 0; ks < 4; ks++) {
            const uint32_t ksoff = (uint32_t)(ks * 16) * 2;
            uint32_t ah[4][4];
#pragma unroll
            for (int mt = 0; mt < 4; mt++)
                ldm_x4(ah[mt], tA + aoff + ksoff + (uint32_t)(mt * 16 * SA) * 2);
#pragma unroll
            for (int g = 0; g < 2; g++) {
                uint32_t bb[4];
                ldm_x4(bb, tB + boff + ksoff + (uint32_t)(g * 16 * SA) * 2);
#pragma unroll
                for (int mt = 0; mt < 4; mt++) {
                    mma_f16(acc[mt][2 * g],     ah[mt], bb[0], bb[1]);
                    mma_f16(acc[mt][2 * g + 1], ah[mt], bb[2], bb[3]);
                }
            }
        }
    }

    const int rowg = lane >> 2, colg = (lane & 3) * 2;
#pragma unroll
    for (int mt = 0; mt < 4; mt++) {
#pragma unroll
        for (int nt = 0; nt < 4; nt++) {
            int r = m0 + warp_m * 64 + mt * 16 + rowg;
            int cc = n0 + warp_n * 32 + nt * 8 + colg;
            *(float2*)(C + (size_t)r * KDIM + cc) =
                make_float2(acc[mt][nt][0], acc[mt][nt][1]);
            *(float2*)(C + (size_t)(r + 8) * KDIM + cc) =
                make_float2(acc[mt][nt][2], acc[mt][nt][3]);
        }
    }
}

/* ========== fp16 HMMA causal flash attention, prefetched KV ============== */
#define FKS 136
#define FVS 72
#define OFF_QH 0
#define OFF_QL (128 * FKS)
#define OFF_K0 (2 * 128 * FKS)
#define OFF_V0 (OFF_K0 + 64 * FKS)
#define KVSTG  (64 * FKS + 128 * FVS)   /* 17920 halfwords                  */
#define FL_SMEM ((OFF_K0 + 2 * KVSTG) * 2)   /* 141312 B                    */

__global__ void __launch_bounds__(256, 1) flash_hmma(const __half* __restrict__ QH,
                                                     const __half* __restrict__ QL,
                                                     const __half* __restrict__ Kf,
                                                     const __half* __restrict__ VT) {
    extern __shared__ char shf[];
    const uint32_t sb = smem_u32(shf);
    const int tid = threadIdx.x, lane = tid & 31, wid = tid >> 5;
    const int qb = (int)gridDim.x - 1 - (int)blockIdx.x;  /* heavy first */
    const int h = blockIdx.y, b = blockIdx.z;
    const int q0 = qb * 128;
    const int wm0 = wid * 16;
    const float scale = 0.08838834764831845f;

    /* ---- Q tiles via cp.async ---- */
    const __half* QHg = QH + (size_t)(b * SQ + q0) * HID + h * HD;
    const __half* QLg = QL + (size_t)(b * SQ + q0) * HID + h * HD;
#pragma unroll
    for (int it = 0; it < 8; it++) {
        int idx = tid + it * 256;
        int r = idx >> 4, c8 = (idx & 15) << 3;
        cp16(sb + (uint32_t)(OFF_QH + r * FKS + c8) * 2, QHg + (size_t)r * HID + c8);
        cp16(sb + (uint32_t)(OFF_QL + r * FKS + c8) * 2, QLg + (size_t)r * HID + c8);
    }

    const __half* Kg0 = Kf + (size_t)(b * SQ) * HID + h * HD;
    const __half* Vg0 = VT + (size_t)((b * NHEAD + h) * HD) * SQ;

    /* issue K/V block 0 into buf 0 (grouped with Q copies) */
    {
#pragma unroll
        for (int it = 0; it < 4; it++) {
            int u = tid + it * 256;
            int r = u >> 4, c8 = (u & 15) << 3;
            cp16(sb + (uint32_t)(OFF_K0 + r * FKS + c8) * 2, Kg0 + (size_t)r * HID + c8);
        }
#pragma unroll
        for (int it = 0; it < 4; it++) {
            int u = tid + it * 256;
            int d = u >> 3, c8 = (u & 7) << 3;
            cp16(sb + (uint32_t)(OFF_V0 + d * FVS + c8) * 2, Vg0 + (size_t)d * SQ + c8);
        }
        cp_commit();
    }

    const uint32_t aBaseH = sb + 2u * (OFF_QH + (wm0 + (lane & 15)) * FKS + ((lane >> 4) << 3));
    const uint32_t aBaseL = sb + 2u * (OFF_QL + (wm0 + (lane & 15)) * FKS + ((lane >> 4) << 3));
    const int krow = (lane & 7) + ((lane >> 4) << 3);
    uint32_t kBase[2], vBase[2];
#pragma unroll
    for (int bu = 0; bu < 2; bu++) {
        kBase[bu] = sb + 2u * (OFF_K0 + bu * KVSTG + krow * FKS + (lane & 8));
        vBase[bu] = sb + 2u * (OFF_V0 + bu * KVSTG + krow * FVS + (lane & 8));
    }

    float acc_o[16][4];
#pragma unroll
    for (int i = 0; i < 16; i++)
#pragma unroll
        for (int j = 0; j < 4; j++) acc_o[i][j] = 0.0f;
    float m0r = -1e30f, m1r = -1e30f, l0r = 0.0f, l1r = 0.0f;

    const int kb_max = 2 * qb + 1;
    const int r0g = q0 + wm0 + (lane >> 2);
    const int r1g = r0g + 8;

    for (int kb = 0; kb <= kb_max; kb++) {
        const int k0 = kb * 64;
        cp_wait<0>();
        __syncthreads();

        /* prefetch next block into the other buffer */
        if (kb < kb_max) {
            const int kn = (kb + 1) * 64;
            const uint32_t bo = (uint32_t)(((kb + 1) & 1) * KVSTG) * 2;
#pragma unroll
            for (int it = 0; it < 4; it++) {
                int u = tid + it * 256;
                int r = u >> 4, c8 = (u & 15) << 3;
                cp16(sb + (uint32_t)(OFF_K0 + r * FKS + c8) * 2 + bo,
                     Kg0 + (size_t)(kn + r) * HID + c8);
            }
#pragma unroll
            for (int it = 0; it < 4; it++) {
                int u = tid + it * 256;
                int d = u >> 3, c8 = (u & 7) << 3;
                cp16(sb + (uint32_t)(OFF_V0 + d * FVS + c8) * 2 + bo,
                     Vg0 + (size_t)d * SQ + kn + c8);
            }
            cp_commit();
        }

        if (k0 > q0 + wm0) continue;
        const uint32_t kB = kBase[kb & 1], vB = vBase[kb & 1];

        float accs[8][4];
#pragma unroll
        for (int i = 0; i < 8; i++)
#pragma unroll
            for (int j = 0; j < 4; j++) accs[i][j] = 0.0f;
#pragma unroll
        for (int ks = 0; ks < 8; ks++) {
            uint32_t qh[4], ql[4];
            ldm_x4(qh, aBaseH + ks * 32);
            ldm_x4(ql, aBaseL + ks * 32);
            uint32_t kk4[4][4];
#pragma unroll
            for (int ng = 0; ng < 4; ng++)
                ldm_x4(kk4[ng], kB + (uint32_t)(ng * 16 * FKS) * 2 + ks * 32);
#pragma unroll
            for (int ng = 0; ng < 4; ng++) {
                mma_f16(accs[2 * ng],     qh, kk4[ng][0], kk4[ng][1]);
                mma_f16(accs[2 * ng + 1], qh, kk4[ng][2], kk4[ng][3]);
            }
#pragma unroll
            for (int ng = 0; ng < 4; ng++) {
                mma_f16(accs[2 * ng],     ql, kk4[ng][0], kk4[ng][1]);
                mma_f16(accs[2 * ng + 1], ql, kk4[ng][2], kk4[ng][3]);
            }
        }

#pragma unroll
        for (int nt = 0; nt < 8; nt++) {
            int cb = k0 + nt * 8 + (lane & 3) * 2;
            accs[nt][0] = accs[nt][0] * scale + ((cb     > r0g) ? -1e9f : 0.0f);
            accs[nt][1] = accs[nt][1] * scale + ((cb + 1 > r0g) ? -1e9f : 0.0f);
            accs[nt][2] = accs[nt][2] * scale + ((cb     > r1g) ? -1e9f : 0.0f);
            accs[nt][3] = accs[nt][3] * scale + ((cb + 1 > r1g) ? -1e9f : 0.0f);
        }

        float mx0 = -1e30f, mx1 = -1e30f;
#pragma unroll
        for (int nt = 0; nt < 8; nt++) {
            mx0 = fmaxf(mx0, fmaxf(accs[nt][0], accs[nt][1]));
            mx1 = fmaxf(mx1, fmaxf(accs[nt][2], accs[nt][3]));
        }
        mx0 = fmaxf(mx0, __shfl_xor_sync(0xffffffffu, mx0, 1));
        mx0 = fmaxf(mx0, __shfl_xor_sync(0xffffffffu, mx0, 2));
        mx1 = fmaxf(mx1, __shfl_xor_sync(0xffffffffu, mx1, 1));
        mx1 = fmaxf(mx1, __shfl_xor_sync(0xffffffffu, mx1, 2));
        float mn0 = fmaxf(m0r, mx0), mn1 = fmaxf(m1r, mx1);
        float al0 = __expf(m0r - mn0), al1 = __expf(m1r - mn1);
        m0r = mn0; m1r = mn1;
        float rs0 = 0.0f, rs1 = 0.0f;
#pragma unroll
        for (int nt = 0; nt < 8; nt++) {
            accs[nt][0] = __expf(accs[nt][0] - mn0);
            accs[nt][1] = __expf(accs[nt][1] - mn0);
            accs[nt][2] = __expf(accs[nt][2] - mn1);
            accs[nt][3] = __expf(accs[nt][3] - mn1);
            rs0 += accs[nt][0] + accs[nt][1];
            rs1 += accs[nt][2] + accs[nt][3];
        }
        rs0 += __shfl_xor_sync(0xffffffffu, rs0, 1);
        rs0 += __shfl_xor_sync(0xffffffffu, rs0, 2);
        rs1 += __shfl_xor_sync(0xffffffffu, rs1, 1);
        rs1 += __shfl_xor_sync(0xffffffffu, rs1, 2);
        l0r = l0r * al0 + rs0;
        l1r = l1r * al1 + rs1;
#pragma unroll
        for (int i = 0; i < 16; i++) {
            acc_o[i][0] *= al0; acc_o[i][1] *= al0;
            acc_o[i][2] *= al1; acc_o[i][3] *= al1;
        }

        uint32_t ph[4][4];
#pragma unroll
        for (int kk = 0; kk < 4; kk++) {
            int n0t = 2 * kk, n1t = 2 * kk + 1;
            ph[kk][0] = pack_h(accs[n0t][0], accs[n0t][1]);
            ph[kk][1] = pack_h(accs[n0t][2], accs[n0t][3]);
            ph[kk][2] = pack_h(accs[n1t][0], accs[n1t][1]);
            ph[kk][3] = pack_h(accs[n1t][2], accs[n1t][3]);
        }

#pragma unroll
        for (int kk = 0; kk < 4; kk++) {
#pragma unroll
            for (int gb = 0; gb < 8; gb += 4) {
                uint32_t vt[4][4];
#pragma unroll
                for (int g = 0; g < 4; g++)
                    ldm_x4(vt[g], vB + (uint32_t)((gb + g) * 16 * FVS) * 2 + kk * 32);
#pragma unroll
                for (int g = 0; g < 4; g++) {
                    mma_f16(acc_o[2 * (gb + g)],     ph[kk], vt[g][0], vt[g][1]);
                    mma_f16(acc_o[2 * (gb + g) + 1], ph[kk], vt[g][2], vt[g][3]);
                }
            }
        }
    }

    /* ---- epilogue: attention output as single fp16 ---- */
    float inv0 = 1.0f / l0r, inv1 = 1.0f / l1r;
    size_t base0 = (size_t)(b * SQ + r0g) * HID + h * HD;
    size_t base1 = base0 + (size_t)8 * HID;
#pragma unroll
    for (int nto = 0; nto < 16; nto++) {
        int c = nto * 8 + (lane & 3) * 2;
        *(uint32_t*)(g_Af + base0 + c) = pack_h(acc_o[nto][0] * inv0, acc_o[nto][1] * inv0);
        *(uint32_t*)(g_Af + base1 + c) = pack_h(acc_o[nto][2] * inv1, acc_o[nto][3] * inv1);
    }
}

/* ---------------- launcher ---------------------------------------------- */
extern "C" void kernel_launch(void* const* d_in, const int* in_sizes, int n_in,
                              void* d_out, int out_size) {
    (void)n_in; (void)out_size;
    const float* x   = (const float*)d_in[0];
    const float* cpq = (const float*)d_in[1];
    const float* cpk = (const float*)d_in[2];
    const float* cpv = (const float*)d_in[3];
    const float* cpo = (const float*)d_in[4];
    float* out = (float*)d_out;
    int ncp = in_sizes[1];

    __half *pWf, *pXf, *pAf, *pQH, *pQL, *pKf, *pVT;
    float *pQ, *pK, *pV;
    cudaGetSymbolAddress((void**)&pWf, g_Wf);
    cudaGetSymbolAddress((void**)&pXf, g_Xf);
    cudaGetSymbolAddress((void**)&pAf, g_Af);
    cudaGetSymbolAddress((void**)&pQ, g_Q);
    cudaGetSymbolAddress((void**)&pK, g_K);
    cudaGetSymbolAddress((void**)&pV, g_V);
    cudaGetSymbolAddress((void**)&pQH, g_QH);
    cudaGetSymbolAddress((void**)&pQL, g_QL);
    cudaGetSymbolAddress((void**)&pKf, g_Kf);
    cudaGetSymbolAddress((void**)&pVT, g_VT);

    build_weights<<<(NW + 255) / 256, 256>>>(cpq, cpk, cpv, cpo, ncp);
    split_x<<<(MROWS * HID / 4 + 255) / 256, 256>>>(x);

    cudaFuncSetAttribute(gemm_hmma, cudaFuncAttributeMaxDynamicSharedMemorySize,
                         GEMM_SMEM);
    dim3 gg(HID / 128, MROWS / 128);
    gemm_hmma<<<gg, 256, GEMM_SMEM>>>(pXf, pWf + 0 * (size_t)NW, pQ);
    gemm_hmma<<<gg, 256, GEMM_SMEM>>>(pXf, pWf + 1 * (size_t)NW, pK);
    gemm_hmma<<<gg, 256, GEMM_SMEM>>>(pXf, pWf + 2 * (size_t)NW, pV);

    cvt_qk<<<(MROWS * HID / 4 + 255) / 256, 256>>>(pQ, pK);
    vtrans<<<dim3(SQ / 32, HD / 32, NB * NHEAD), dim3(32, 8)>>>(pV);

    cudaFuncSetAttribute(flash_hmma, cudaFuncAttributeMaxDynamicSharedMemorySize,
                         FL_SMEM);
    flash_hmma<<<dim3(SQ / 128, NHEAD, NB), 256, FL_SMEM>>>(pQH, pQL, pKf, pVT);

    gemm_hmma<<<gg, 256, GEMM_SMEM>>>(pAf, pWf + 3 * (size_t)NW, out);
}

// round 14
// speedup vs baseline: 2.9609x; 1.1530x over previous
#include <cuda_runtime.h>
#include <cuda_fp16.h>
#include <math.h>
#include <stdint.h>

#define HID   2048
#define NB    2
#define SQ    2048
#define NHEAD 16
#define HD    128
#define MROWS (NB * SQ)        /* 4096 */
#define NW    (HID * HID)      /* 4194304 */
#define KDIM  2048

/* ---------------- scratch (device globals; no allocation allowed) -------- */
__device__ __half g_Wf[4][NW];          /* weights, single fp16             */
__device__ __half g_Xf[MROWS * HID];    /* activations, single fp16         */
__device__ __half g_Af[MROWS * HID];    /* attn output, single fp16         */
__device__ __half g_Qf[MROWS * HID];    /* Q fp16                           */
__device__ __half g_Kf[MROWS * HID];    /* K fp16                           */
__device__ float  g_V [MROWS * HID];    /* V fp32 (pre-transpose)           */
__device__ __half g_VT[MROWS * HID];    /* V fp16, transposed [b,h,d,s]     */

__device__ __forceinline__ uint32_t smem_u32(const void* p) {
    uint32_t a;
    asm("{ .reg .u64 t; cvta.to.shared.u64 t, %1; cvt.u32.u64 %0, t; }"
        : "=r"(a) : "l"(p));
    return a;
}
__device__ __forceinline__ void ldm_x4(uint32_t* r, uint32_t addr) {
    asm volatile("ldmatrix.sync.aligned.m8n8.x4.shared.b16 {%0,%1,%2,%3}, [%4];"
                 : "=r"(r[0]), "=r"(r[1]), "=r"(r[2]), "=r"(r[3]) : "r"(addr));
}
__device__ __forceinline__ void mma_f16(float* d, const uint32_t* a,
                                        uint32_t b0, uint32_t b1) {
    asm volatile("mma.sync.aligned.m16n8k16.row.col.f32.f16.f16.f32 "
                 "{%0,%1,%2,%3},{%4,%5,%6,%7},{%8,%9},{%0,%1,%2,%3};"
                 : "+f"(d[0]), "+f"(d[1]), "+f"(d[2]), "+f"(d[3])
                 : "r"(a[0]), "r"(a[1]), "r"(a[2]), "r"(a[3]), "r"(b0), "r"(b1));
}
__device__ __forceinline__ uint2 cvt4h(float4 v) {
    __half2 h0 = __float22half2_rn(make_float2(v.x, v.y));
    __half2 h1 = __float22half2_rn(make_float2(v.z, v.w));
    return make_uint2(*(uint32_t*)&h0, *(uint32_t*)&h1);
}
__device__ __forceinline__ uint32_t pack_h(float a, float b) {
    __half2 h = __float22half2_rn(make_float2(a, b));
    return *(uint32_t*)&h;
}
__device__ __forceinline__ void cp16(uint32_t smem, const void* g) {
    asm volatile("cp.async.cg.shared.global [%0], [%1], 16;"
                 :: "r"(smem), "l"(g) : "memory");
}
__device__ __forceinline__ void cp_commit() {
    asm volatile("cp.async.commit_group;" ::: "memory");
}
template <int N>
__device__ __forceinline__ void cp_wait() {
    asm volatile("cp.async.wait_group %0;" :: "n"(N) : "memory");
}

/* ---------------- weight reconstruction -> single fp16 ------------------- */
__global__ void build_weights(const float* __restrict__ cpq,
                              const float* __restrict__ cpk,
                              const float* __restrict__ cpv,
                              const float* __restrict__ cpo,
                              int ncp) {
    int i = blockIdx.x * 256 + threadIdx.x;
    if (i >= NW) return;
    const float dT = 1.0f / (float)(NW - 1);
    const float dX = 1.0f / (float)(ncp - 1);
    float t = (float)i * dT;
    int j = (int)((double)t * (double)(ncp - 1));
    if (j > ncp - 2) j = ncp - 2;
    if (j < 0) j = 0;
    while (j < ncp - 2 && (float)(j + 1) * dX <= t) j++;
    while (j > 0 && (float)j * dX > t) j--;
    float x0 = (float)j * dX;
    float x1 = (float)(j + 1) * dX;
    float f  = (t - x0) / (x1 - x0);
    const float* cps[4] = {cpq, cpk, cpv, cpo};
#pragma unroll
    for (int w = 0; w < 4; w++) {
        float a = cps[w][j];
        g_Wf[w][i] = __float2half_rn(fmaf(cps[w][j + 1] - a, f, a));
    }
}

/* ---------------- convert hidden_states -> single fp16 ------------------- */
__global__ void split_x(const float* __restrict__ x) {
    int i = blockIdx.x * 256 + threadIdx.x;
    if (i >= MROWS * HID / 4) return;
    float4 v = *(const float4*)(x + 4 * (size_t)i);
    *(uint2*)(g_Xf + 4 * (size_t)i) = cvt4h(v);
}

/* ---------------- V fp32 [b,s,h,d] -> VT fp16 [b,h,d,s] ------------------ */
__global__ void vtrans(const float* __restrict__ V) {
    __shared__ __half t[32][33];
    const int tx = threadIdx.x, ty = threadIdx.y;      /* 32 x 8 */
    const int s0 = blockIdx.x * 32, d0 = blockIdx.y * 32;
    const int bh = blockIdx.z;
    const int b = bh >> 4, h = bh & 15;
#pragma unroll
    for (int k = 0; k < 4; k++) {
        int srow = s0 + ty + 8 * k;
        t[ty + 8 * k][tx] =
            __float2half_rn(V[(size_t)(b * SQ + srow) * HID + h * HD + d0 + tx]);
    }
    __syncthreads();
#pragma unroll
    for (int k = 0; k < 4; k++) {
        int drow = d0 + ty + 8 * k;
        g_VT[(size_t)(bh * HD + drow) * SQ + s0 + tx] = t[tx][ty + 8 * k];
    }
}

/* == fp16 HMMA GEMM: C = A*B^T.  CTA 128x128, 256 thr, KC=64 ============= */
/* fused=1: blockIdx.z in {0,1,2} selects weight (Bbase + z*NW) and output  */
/*          (z=0 -> o16a fp16, z=1 -> o16b fp16, z=2 -> o32 fp32).          */
/* fused=0: B = Bbase, output fp32 to o32.                                  */
#define KC      64
#define NCHUNK  (KDIM / KC)
#define SA      72                      /* halfwords per smem row (144 B)   */
#define OFF_A   0
#define OFF_B   (128 * SA)
#define STG_HW  (2 * 128 * SA)
#define STG_B   (STG_HW * 2)            /* 36864 B                          */
#define GEMM_SMEM (2 * STG_B)           /* 73728 B                          */

__global__ void __launch_bounds__(256, 2) gemm_hmma(const __half* __restrict__ A,
                                                    const __half* __restrict__ Bbase,
                                                    __half* __restrict__ o16a,
                                                    __half* __restrict__ o16b,
                                                    float* __restrict__ o32,
                                                    int fused) {
    extern __shared__ char shg[];
    const uint32_t sb = smem_u32(shg);
    const int tid = threadIdx.x;
    const int lane = tid & 31, wid = tid >> 5;
    const int warp_m = wid >> 2;
    const int warp_n = wid & 3;
    const int m0 = blockIdx.y * 128, n0 = blockIdx.x * 128;
    const int z = fused ? (int)blockIdx.z : 3;
    const __half* B = fused ? (Bbase + (size_t)z * NW) : Bbase;
    __half* out16 = (z == 0) ? o16a : (z == 1) ? o16b : (__half*)0;
    float*  out32 = (z >= 2) ? o32 : (float*)0;

    const int rL = tid >> 3;                  /* 0..31                      */
    const int cL = (tid & 7) << 3;            /* halfword col 0..56         */
    const __half* gA = A + (size_t)(m0 + rL) * KDIM + cL;
    const __half* gB = B + (size_t)(n0 + rL) * KDIM + cL;
    uint32_t dA[4], dB[4];
#pragma unroll
    for (int p = 0; p < 4; p++) {
        dA[p] = sb + (uint32_t)((rL + 32 * p) * SA + cL) * 2;
        dB[p] = dA[p] + (uint32_t)OFF_B * 2;
    }

    float acc[4][4][4];
#pragma unroll
    for (int i = 0; i < 4; i++)
#pragma unroll
        for (int j = 0; j < 4; j++)
#pragma unroll
            for (int q = 0; q < 4; q++) acc[i][j][q] = 0.0f;

    const int rowA = lane & 15, colA8 = (lane >= 16) ? 8 : 0;
    const int rowB = (lane & 7) + ((lane >= 16) ? 8 : 0);
    const int colB8 = (lane & 8) ? 8 : 0;
    const uint32_t aoff = (uint32_t)((warp_m * 64 + rowA) * SA + colA8) * 2;
    const uint32_t boff = (uint32_t)((warp_n * 32 + rowB) * SA + colB8) * 2;

    {
#pragma unroll
        for (int p = 0; p < 4; p++) {
            cp16(dA[p], gA + (size_t)(32 * p) * KDIM);
            cp16(dB[p], gB + (size_t)(32 * p) * KDIM);
        }
        cp_commit();
    }

    for (int c = 0; c < NCHUNK; c++) {
        cp_wait<0>();
        __syncthreads();
        if (c + 1 < NCHUNK) {
            const uint32_t st = ((c + 1) & 1) * STG_B;
            const int kc = (c + 1) * KC;
#pragma unroll
            for (int p = 0; p < 4; p++) {
                cp16(dA[p] + st, gA + (size_t)(32 * p) * KDIM + kc);
                cp16(dB[p] + st, gB + (size_t)(32 * p) * KDIM + kc);
            }
            cp_commit();
        }

        const uint32_t stg = sb + (c & 1) * STG_B;
        const uint32_t tA = stg + OFF_A * 2, tB = stg + OFF_B * 2;
#pragma unroll
        for (int ks = 0; ks < 4; ks++) {
            const uint32_t ksoff = (uint32_t)(ks * 16) * 2;
            uint32_t ah[4][4];
#pragma unroll
            for (int mt = 0; mt < 4; mt++)
                ldm_x4(ah[mt], tA + aoff + ksoff + (uint32_t)(mt * 16 * SA) * 2);
#pragma unroll
            for (int g = 0; g < 2; g++) {
                uint32_t bb[4];
                ldm_x4(bb, tB + boff + ksoff + (uint32_t)(g * 16 * SA) * 2);
#pragma unroll
                for (int mt = 0; mt < 4; mt++) {
                    mma_f16(acc[mt][2 * g],     ah[mt], bb[0], bb[1]);
                    mma_f16(acc[mt][2 * g + 1], ah[mt], bb[2], bb[3]);
                }
            }
        }
    }

    const int rowg = lane >> 2, colg = (lane & 3) * 2;
    if (out16) {
#pragma unroll
        for (int mt = 0; mt < 4; mt++) {
#pragma unroll
            for (int nt = 0; nt < 4; nt++) {
                int r = m0 + warp_m * 64 + mt * 16 + rowg;
                int cc = n0 + warp_n * 32 + nt * 8 + colg;
                *(uint32_t*)(out16 + (size_t)r * KDIM + cc) =
                    pack_h(acc[mt][nt][0], acc[mt][nt][1]);
                *(uint32_t*)(out16 + (size_t)(r + 8) * KDIM + cc) =
                    pack_h(acc[mt][nt][2], acc[mt][nt][3]);
            }
        }
    } else {
#pragma unroll
        for (int mt = 0; mt < 4; mt++) {
#pragma unroll
            for (int nt = 0; nt < 4; nt++) {
                int r = m0 + warp_m * 64 + mt * 16 + rowg;
                int cc = n0 + warp_n * 32 + nt * 8 + colg;
                *(float2*)(out32 + (size_t)r * KDIM + cc) =
                    make_float2(acc[mt][nt][0], acc[mt][nt][1]);
                *(float2*)(out32 + (size_t)(r + 8) * KDIM + cc) =
                    make_float2(acc[mt][nt][2], acc[mt][nt][3]);
            }
        }
    }
}

/* ========== fp16 HMMA causal flash attention, single-Q, prefetched KV ==== */
#define FKS 136
#define FVS 72
#define OFF_Q  0
#define OFF_K0 (128 * FKS)
#define OFF_V0 (OFF_K0 + 64 * FKS)
#define KVSTG  (64 * FKS + 128 * FVS)   /* 17920 halfwords                  */
#define FL_SMEM ((128 * FKS + 2 * KVSTG) * 2)   /* 106496 B                 */

__global__ void __launch_bounds__(256, 1) flash_hmma(const __half* __restrict__ Qf,
                                                     const __half* __restrict__ Kf,
                                                     const __half* __restrict__ VT) {
    extern __shared__ char shf[];
    const uint32_t sb = smem_u32(shf);
    const int tid = threadIdx.x, lane = tid & 31, wid = tid >> 5;
    const int qb = (int)gridDim.x - 1 - (int)blockIdx.x;  /* heavy first */
    const int h = blockIdx.y, b = blockIdx.z;
    const int q0 = qb * 128;
    const int wm0 = wid * 16;
    const float scale = 0.08838834764831845f;

    /* ---- Q tile via cp.async ---- */
    const __half* Qg = Qf + (size_t)(b * SQ + q0) * HID + h * HD;
#pragma unroll
    for (int it = 0; it < 8; it++) {
        int idx = tid + it * 256;
        int r = idx >> 4, c8 = (idx & 15) << 3;
        cp16(sb + (uint32_t)(OFF_Q + r * FKS + c8) * 2, Qg + (size_t)r * HID + c8);
    }

    const __half* Kg0 = Kf + (size_t)(b * SQ) * HID + h * HD;
    const __half* Vg0 = VT + (size_t)((b * NHEAD + h) * HD) * SQ;

    /* issue K/V block 0 into buf 0 */
    {
#pragma unroll
        for (int it = 0; it < 4; it++) {
            int u = tid + it * 256;
            int r = u >> 4, c8 = (u & 15) << 3;
            cp16(sb + (uint32_t)(OFF_K0 + r * FKS + c8) * 2, Kg0 + (size_t)r * HID + c8);
        }
#pragma unroll
        for (int it = 0; it < 4; it++) {
            int u = tid + it * 256;
            int d = u >> 3, c8 = (u & 7) << 3;
            cp16(sb + (uint32_t)(OFF_V0 + d * FVS + c8) * 2, Vg0 + (size_t)d * SQ + c8);
        }
        cp_commit();
    }

    const uint32_t aBase = sb + 2u * (OFF_Q + (wm0 + (lane & 15)) * FKS + ((lane >> 4) << 3));
    const int krow = (lane & 7) + ((lane >> 4) << 3);
    uint32_t kBase[2], vBase[2];
#pragma unroll
    for (int bu = 0; bu < 2; bu++) {
        kBase[bu] = sb + 2u * (OFF_K0 + bu * KVSTG + krow * FKS + (lane & 8));
        vBase[bu] = sb + 2u * (OFF_V0 + bu * KVSTG + krow * FVS + (lane & 8));
    }

    float acc_o[16][4];
#pragma unroll
    for (int i = 0; i < 16; i++)
#pragma unroll
        for (int j = 0; j < 4; j++) acc_o[i][j] = 0.0f;
    float m0r = -1e30f, m1r = -1e30f, l0r = 0.0f, l1r = 0.0f;

    const int kb_max = 2 * qb + 1;
    const int r0g = q0 + wm0 + (lane >> 2);
    const int r1g = r0g + 8;

    for (int kb = 0; kb <= kb_max; kb++) {
        const int k0 = kb * 64;
        cp_wait<0>();
        __syncthreads();

        if (kb < kb_max) {
            const int kn = (kb + 1) * 64;
            const uint32_t bo = (uint32_t)(((kb + 1) & 1) * KVSTG) * 2;
#pragma unroll
            for (int it = 0; it < 4; it++) {
                int u = tid + it * 256;
                int r = u >> 4, c8 = (u & 15) << 3;
                cp16(sb + (uint32_t)(OFF_K0 + r * FKS + c8) * 2 + bo,
                     Kg0 + (size_t)(kn + r) * HID + c8);
            }
#pragma unroll
            for (int it = 0; it < 4; it++) {
                int u = tid + it * 256;
                int d = u >> 3, c8 = (u & 7) << 3;
                cp16(sb + (uint32_t)(OFF_V0 + d * FVS + c8) * 2 + bo,
                     Vg0 + (size_t)d * SQ + kn + c8);
            }
            cp_commit();
        }

        if (k0 > q0 + wm0) continue;
        const uint32_t kB = kBase[kb & 1], vB = vBase[kb & 1];

        float accs[8][4];
#pragma unroll
        for (int i = 0; i < 8; i++)
#pragma unroll
            for (int j = 0; j < 4; j++) accs[i][j] = 0.0f;
#pragma unroll
        for (int ks = 0; ks < 8; ks++) {
            uint32_t qh[4];
            ldm_x4(qh, aBase + ks * 32);
            uint32_t kk4[4][4];
#pragma unroll
            for (int ng = 0; ng < 4; ng++)
                ldm_x4(kk4[ng], kB + (uint32_t)(ng * 16 * FKS) * 2 + ks * 32);
#pragma unroll
            for (int ng = 0; ng < 4; ng++) {
                mma_f16(accs[2 * ng],     qh, kk4[ng][0], kk4[ng][1]);
                mma_f16(accs[2 * ng + 1], qh, kk4[ng][2], kk4[ng][3]);
            }
        }

#pragma unroll
        for (int nt = 0; nt < 8; nt++) {
            int cb = k0 + nt * 8 + (lane & 3) * 2;
            accs[nt][0] = accs[nt][0] * scale + ((cb     > r0g) ? -1e9f : 0.0f);
            accs[nt][1] = accs[nt][1] * scale + ((cb + 1 > r0g) ? -1e9f : 0.0f);
            accs[nt][2] = accs[nt][2] * scale + ((cb     > r1g) ? -1e9f : 0.0f);
            accs[nt][3] = accs[nt][3] * scale + ((cb + 1 > r1g) ? -1e9f : 0.0f);
        }

        float mx0 = -1e30f, mx1 = -1e30f;
#pragma unroll
        for (int nt = 0; nt < 8; nt++) {
            mx0 = fmaxf(mx0, fmaxf(accs[nt][0], accs[nt][1]));
            mx1 = fmaxf(mx1, fmaxf(accs[nt][2], accs[nt][3]));
        }
        mx0 = fmaxf(mx0, __shfl_xor_sync(0xffffffffu, mx0, 1));
        mx0 = fmaxf(mx0, __shfl_xor_sync(0xffffffffu, mx0, 2));
        mx1 = fmaxf(mx1, __shfl_xor_sync(0xffffffffu, mx1, 1));
        mx1 = fmaxf(mx1, __shfl_xor_sync(0xffffffffu, mx1, 2));
        float mn0 = fmaxf(m0r, mx0), mn1 = fmaxf(m1r, mx1);
        float al0 = __expf(m0r - mn0), al1 = __expf(m1r - mn1);
        m0r = mn0; m1r = mn1;
        float rs0 = 0.0f, rs1 = 0.0f;
#pragma unroll
        for (int nt = 0; nt < 8; nt++) {
            accs[nt][0] = __expf(accs[nt][0] - mn0);
            accs[nt][1] = __expf(accs[nt][1] - mn0);
            accs[nt][2] = __expf(accs[nt][2] - mn1);
            accs[nt][3] = __expf(accs[nt][3] - mn1);
            rs0 += accs[nt][0] + accs[nt][1];
            rs1 += accs[nt][2] + accs[nt][3];
        }
        rs0 += __shfl_xor_sync(0xffffffffu, rs0, 1);
        rs0 += __shfl_xor_sync(0xffffffffu, rs0, 2);
        rs1 += __shfl_xor_sync(0xffffffffu, rs1, 1);
        rs1 += __shfl_xor_sync(0xffffffffu, rs1, 2);
        l0r = l0r * al0 + rs0;
        l1r = l1r * al1 + rs1;
#pragma unroll
        for (int i = 0; i < 16; i++) {
            acc_o[i][0] *= al0; acc_o[i][1] *= al0;
            acc_o[i][2] *= al1; acc_o[i][3] *= al1;
        }

        uint32_t ph[4][4];
#pragma unroll
        for (int kk = 0; kk < 4; kk++) {
            int n0t = 2 * kk, n1t = 2 * kk + 1;
            ph[kk][0] = pack_h(accs[n0t][0], accs[n0t][1]);
            ph[kk][1] = pack_h(accs[n0t][2], accs[n0t][3]);
            ph[kk][2] = pack_h(accs[n1t][0], accs[n1t][1]);
            ph[kk][3] = pack_h(accs[n1t][2], accs[n1t][3]);
        }

#pragma unroll
        for (int kk = 0; kk < 4; kk++) {
#pragma unroll
            for (int gb = 0; gb < 8; gb += 4) {
                uint32_t vt[4][4];
#pragma unroll
                for (int g = 0; g < 4; g++)
                    ldm_x4(vt[g], vB + (uint32_t)((gb + g) * 16 * FVS) * 2 + kk * 32);
#pragma unroll
                for (int g = 0; g < 4; g++) {
                    mma_f16(acc_o[2 * (gb + g)],     ph[kk], vt[g][0], vt[g][1]);
                    mma_f16(acc_o[2 * (gb + g) + 1], ph[kk], vt[g][2], vt[g][3]);
                }
            }
        }
    }

    float inv0 = 1.0f / l0r, inv1 = 1.0f / l1r;
    size_t base0 = (size_t)(b * SQ + r0g) * HID + h * HD;
    size_t base1 = base0 + (size_t)8 * HID;
#pragma unroll
    for (int nto = 0; nto < 16; nto++) {
        int c = nto * 8 + (lane & 3) * 2;
        *(uint32_t*)(g_Af + base0 + c) = pack_h(acc_o[nto][0] * inv0, acc_o[nto][1] * inv0);
        *(uint32_t*)(g_Af + base1 + c) = pack_h(acc_o[nto][2] * inv1, acc_o[nto][3] * inv1);
    }
}

/* ---------------- launcher ---------------------------------------------- */
extern "C" void kernel_launch(void* const* d_in, const int* in_sizes, int n_in,
                              void* d_out, int out_size) {
    (void)n_in; (void)out_size;
    const float* x   = (const float*)d_in[0];
    const float* cpq = (const float*)d_in[1];
    const float* cpk = (const float*)d_in[2];
    const float* cpv = (const float*)d_in[3];
    const float* cpo = (const float*)d_in[4];
    float* out = (float*)d_out;
    int ncp = in_sizes[1];

    __half *pWf, *pXf, *pAf, *pQf, *pKf, *pVT;
    float *pV;
    cudaGetSymbolAddress((void**)&pWf, g_Wf);
    cudaGetSymbolAddress((void**)&pXf, g_Xf);
    cudaGetSymbolAddress((void**)&pAf, g_Af);
    cudaGetSymbolAddress((void**)&pQf, g_Qf);
    cudaGetSymbolAddress((void**)&pKf, g_Kf);
    cudaGetSymbolAddress((void**)&pV,  g_V);
    cudaGetSymbolAddress((void**)&pVT, g_VT);

    build_weights<<<(NW + 255) / 256, 256>>>(cpq, cpk, cpv, cpo, ncp);
    split_x<<<(MROWS * HID / 4 + 255) / 256, 256>>>(x);

    cudaFuncSetAttribute(gemm_hmma, cudaFuncAttributeMaxDynamicSharedMemorySize,
                         GEMM_SMEM);
    /* fused QKV: z=0 -> Qf (fp16), z=1 -> Kf (fp16), z=2 -> V (fp32) */
    gemm_hmma<<<dim3(HID / 128, MROWS / 128, 3), 256, GEMM_SMEM>>>(
        pXf, pWf, pQf, pKf, pV, 1);

    vtrans<<<dim3(SQ / 32, HD / 32, NB * NHEAD), dim3(32, 8)>>>(pV);

    cudaFuncSetAttribute(flash_hmma, cudaFuncAttributeMaxDynamicSharedMemorySize,
                         FL_SMEM);
    flash_hmma<<<dim3(SQ / 128, NHEAD, NB), 256, FL_SMEM>>>(pQf, pKf, pVT);

    /* O-projection: fp32 out */
    gemm_hmma<<<dim3(HID / 128, MROWS / 128, 1), 256, GEMM_SMEM>>>(
        pAf, pWf + 3 * (size_t)NW, (__half*)0, (__half*)0, out, 0);
}

// round 15
// speedup vs baseline: 2.9790x; 1.0061x over previous
#include <cuda_runtime.h>
#include <cuda_fp16.h>
#include <math.h>
#include <stdint.h>

#define HID   2048
#define NB    2
#define SQ    2048
#define NHEAD 16
#define HD    128
#define MROWS (NB * SQ)        /* 4096 */
#define NW    (HID * HID)      /* 4194304 */
#define KDIM  2048

/* ---------------- scratch (device globals; no allocation allowed) -------- */
__device__ __half g_Wf[4][NW];          /* weights, single fp16             */
__device__ __half g_Xf[MROWS * HID];    /* activations, single fp16         */
__device__ __half g_Af[MROWS * HID];    /* attn output, single fp16         */
__device__ __half g_Qf[MROWS * HID];    /* Q fp16                           */
__device__ __half g_Kf[MROWS * HID];    /* K fp16                           */
__device__ float  g_V [MROWS * HID];    /* V fp32 (pre-transpose)           */
__device__ __half g_VT[MROWS * HID];    /* V fp16, transposed [b,h,d,s]     */

__device__ __forceinline__ uint32_t smem_u32(const void* p) {
    uint32_t a;
    asm("{ .reg .u64 t; cvta.to.shared.u64 t, %1; cvt.u32.u64 %0, t; }"
        : "=r"(a) : "l"(p));
    return a;
}
__device__ __forceinline__ void ldm_x4(uint32_t* r, uint32_t addr) {
    asm volatile("ldmatrix.sync.aligned.m8n8.x4.shared.b16 {%0,%1,%2,%3}, [%4];"
                 : "=r"(r[0]), "=r"(r[1]), "=r"(r[2]), "=r"(r[3]) : "r"(addr));
}
__device__ __forceinline__ void mma_f16(float* d, const uint32_t* a,
                                        uint32_t b0, uint32_t b1) {
    asm volatile("mma.sync.aligned.m16n8k16.row.col.f32.f16.f16.f32 "
                 "{%0,%1,%2,%3},{%4,%5,%6,%7},{%8,%9},{%0,%1,%2,%3};"
                 : "+f"(d[0]), "+f"(d[1]), "+f"(d[2]), "+f"(d[3])
                 : "r"(a[0]), "r"(a[1]), "r"(a[2]), "r"(a[3]), "r"(b0), "r"(b1));
}
__device__ __forceinline__ uint2 cvt4h(float4 v) {
    __half2 h0 = __float22half2_rn(make_float2(v.x, v.y));
    __half2 h1 = __float22half2_rn(make_float2(v.z, v.w));
    return make_uint2(*(uint32_t*)&h0, *(uint32_t*)&h1);
}
__device__ __forceinline__ uint32_t pack_h(float a, float b) {
    __half2 h = __float22half2_rn(make_float2(a, b));
    return *(uint32_t*)&h;
}
__device__ __forceinline__ uint32_t ex2_h2(float a, float b) {
    uint32_t t = pack_h(a, b), r;
    asm("ex2.approx.f16x2 %0, %1;" : "=r"(r) : "r"(t));
    return r;
}
__device__ __forceinline__ void cp16(uint32_t smem, const void* g) {
    asm volatile("cp.async.cg.shared.global [%0], [%1], 16;"
                 :: "r"(smem), "l"(g) : "memory");
}
__device__ __forceinline__ void cp_commit() {
    asm volatile("cp.async.commit_group;" ::: "memory");
}
template <int N>
__device__ __forceinline__ void cp_wait() {
    asm volatile("cp.async.wait_group %0;" :: "n"(N) : "memory");
}

/* ---------------- weight reconstruction -> single fp16 ------------------- */
__global__ void build_weights(const float* __restrict__ cpq,
                              const float* __restrict__ cpk,
                              const float* __restrict__ cpv,
                              const float* __restrict__ cpo,
                              int ncp) {
    int i = blockIdx.x * 256 + threadIdx.x;
    if (i >= NW) return;
    const float dT = 1.0f / (float)(NW - 1);
    const float dX = 1.0f / (float)(ncp - 1);
    float t = (float)i * dT;
    int j = (int)((double)t * (double)(ncp - 1));
    if (j > ncp - 2) j = ncp - 2;
    if (j < 0) j = 0;
    while (j < ncp - 2 && (float)(j + 1) * dX <= t) j++;
    while (j > 0 && (float)j * dX > t) j--;
    float x0 = (float)j * dX;
    float x1 = (float)(j + 1) * dX;
    float f  = (t - x0) / (x1 - x0);
    const float* cps[4] = {cpq, cpk, cpv, cpo};
#pragma unroll
    for (int w = 0; w < 4; w++) {
        float a = cps[w][j];
        g_Wf[w][i] = __float2half_rn(fmaf(cps[w][j + 1] - a, f, a));
    }
}

/* ---------------- convert hidden_states -> single fp16 ------------------- */
__global__ void split_x(const float* __restrict__ x) {
    int i = blockIdx.x * 256 + threadIdx.x;
    if (i >= MROWS * HID / 4) return;
    float4 v = *(const float4*)(x + 4 * (size_t)i);
    *(uint2*)(g_Xf + 4 * (size_t)i) = cvt4h(v);
}

/* ---------------- V fp32 [b,s,h,d] -> VT fp16 [b,h,d,s] ------------------ */
__global__ void vtrans(const float* __restrict__ V) {
    __shared__ __half t[32][33];
    const int tx = threadIdx.x, ty = threadIdx.y;      /* 32 x 8 */
    const int s0 = blockIdx.x * 32, d0 = blockIdx.y * 32;
    const int bh = blockIdx.z;
    const int b = bh >> 4, h = bh & 15;
#pragma unroll
    for (int k = 0; k < 4; k++) {
        int srow = s0 + ty + 8 * k;
        t[ty + 8 * k][tx] =
            __float2half_rn(V[(size_t)(b * SQ + srow) * HID + h * HD + d0 + tx]);
    }
    __syncthreads();
#pragma unroll
    for (int k = 0; k < 4; k++) {
        int drow = d0 + ty + 8 * k;
        g_VT[(size_t)(bh * HD + drow) * SQ + s0 + tx] = t[tx][ty + 8 * k];
    }
}

/* == fp16 HMMA GEMM: C = A*B^T.  CTA 128x128, 256 thr, KC=64 ============= */
#define KC      64
#define NCHUNK  (KDIM / KC)
#define SA      72                      /* halfwords per smem row (144 B)   */
#define OFF_A   0
#define OFF_B   (128 * SA)
#define STG_HW  (2 * 128 * SA)
#define STG_B   (STG_HW * 2)            /* 36864 B                          */
#define GEMM_SMEM (2 * STG_B)           /* 73728 B                          */

__global__ void __launch_bounds__(256, 2) gemm_hmma(const __half* __restrict__ A,
                                                    const __half* __restrict__ Bbase,
                                                    __half* __restrict__ o16a,
                                                    __half* __restrict__ o16b,
                                                    float* __restrict__ o32,
                                                    int fused) {
    extern __shared__ char shg[];
    const uint32_t sb = smem_u32(shg);
    const int tid = threadIdx.x;
    const int lane = tid & 31, wid = tid >> 5;
    const int warp_m = wid >> 2;
    const int warp_n = wid & 3;
    const int m0 = blockIdx.y * 128, n0 = blockIdx.x * 128;
    const int z = fused ? (int)blockIdx.z : 3;
    const __half* B = fused ? (Bbase + (size_t)z * NW) : Bbase;
    __half* out16 = (z == 0) ? o16a : (z == 1) ? o16b : (__half*)0;
    float*  out32 = (z >= 2) ? o32 : (float*)0;

    const int rL = tid >> 3;
    const int cL = (tid & 7) << 3;
    const __half* gA = A + (size_t)(m0 + rL) * KDIM + cL;
    const __half* gB = B + (size_t)(n0 + rL) * KDIM + cL;
    uint32_t dA[4], dB[4];
#pragma unroll
    for (int p = 0; p < 4; p++) {
        dA[p] = sb + (uint32_t)((rL + 32 * p) * SA + cL) * 2;
        dB[p] = dA[p] + (uint32_t)OFF_B * 2;
    }

    float acc[4][4][4];
#pragma unroll
    for (int i = 0; i < 4; i++)
#pragma unroll
        for (int j = 0; j < 4; j++)
#pragma unroll
            for (int q = 0; q < 4; q++) acc[i][j][q] = 0.0f;

    const int rowA = lane & 15, colA8 = (lane >= 16) ? 8 : 0;
    const int rowB = (lane & 7) + ((lane >= 16) ? 8 : 0);
    const int colB8 = (lane & 8) ? 8 : 0;
    const uint32_t aoff = (uint32_t)((warp_m * 64 + rowA) * SA + colA8) * 2;
    const uint32_t boff = (uint32_t)((warp_n * 32 + rowB) * SA + colB8) * 2;

    {
#pragma unroll
        for (int p = 0; p < 4; p++) {
            cp16(dA[p], gA + (size_t)(32 * p) * KDIM);
            cp16(dB[p], gB + (size_t)(32 * p) * KDIM);
        }
        cp_commit();
    }

    for (int c = 0; c < NCHUNK; c++) {
        cp_wait<0>();
        __syncthreads();
        if (c + 1 < NCHUNK) {
            const uint32_t st = ((c + 1) & 1) * STG_B;
            const int kc = (c + 1) * KC;
#pragma unroll
            for (int p = 0; p < 4; p++) {
                cp16(dA[p] + st, gA + (size_t)(32 * p) * KDIM + kc);
                cp16(dB[p] + st, gB + (size_t)(32 * p) * KDIM + kc);
            }
            cp_commit();
        }

        const uint32_t stg = sb + (c & 1) * STG_B;
        const uint32_t tA = stg + OFF_A * 2, tB = stg + OFF_B * 2;
#pragma unroll
        for (int ks = 0; ks < 4; ks++) {
            const uint32_t ksoff = (uint32_t)(ks * 16) * 2;
            uint32_t ah[4][4];
#pragma unroll
            for (int mt = 0; mt < 4; mt++)
                ldm_x4(ah[mt], tA + aoff + ksoff + (uint32_t)(mt * 16 * SA) * 2);
#pragma unroll
            for (int g = 0; g < 2; g++) {
                uint32_t bb[4];
                ldm_x4(bb, tB + boff + ksoff + (uint32_t)(g * 16 * SA) * 2);
#pragma unroll
                for (int mt = 0; mt < 4; mt++) {
                    mma_f16(acc[mt][2 * g],     ah[mt], bb[0], bb[1]);
                    mma_f16(acc[mt][2 * g + 1], ah[mt], bb[2], bb[3]);
                }
            }
        }
    }

    const int rowg = lane >> 2, colg = (lane & 3) * 2;
    if (out16) {
#pragma unroll
        for (int mt = 0; mt < 4; mt++) {
#pragma unroll
            for (int nt = 0; nt < 4; nt++) {
                int r = m0 + warp_m * 64 + mt * 16 + rowg;
                int cc = n0 + warp_n * 32 + nt * 8 + colg;
                *(uint32_t*)(out16 + (size_t)r * KDIM + cc) =
                    pack_h(acc[mt][nt][0], acc[mt][nt][1]);
                *(uint32_t*)(out16 + (size_t)(r + 8) * KDIM + cc) =
                    pack_h(acc[mt][nt][2], acc[mt][nt][3]);
            }
        }
    } else {
#pragma unroll
        for (int mt = 0; mt < 4; mt++) {
#pragma unroll
            for (int nt = 0; nt < 4; nt++) {
                int r = m0 + warp_m * 64 + mt * 16 + rowg;
                int cc = n0 + warp_n * 32 + nt * 8 + colg;
                *(float2*)(out32 + (size_t)r * KDIM + cc) =
                    make_float2(acc[mt][nt][0], acc[mt][nt][1]);
                *(float2*)(out32 + (size_t)(r + 8) * KDIM + cc) =
                    make_float2(acc[mt][nt][2], acc[mt][nt][3]);
            }
        }
    }
}

/* ========== fp16 HMMA causal flash attention, f16x2 exp =================== */
#define FKS 136
#define FVS 72
#define OFF_Q  0
#define OFF_K0 (128 * FKS)
#define OFF_V0 (OFF_K0 + 64 * FKS)
#define KVSTG  (64 * FKS + 128 * FVS)
#define FL_SMEM ((128 * FKS + 2 * KVSTG) * 2)   /* 106496 B                 */

__global__ void __launch_bounds__(256, 1) flash_hmma(const __half* __restrict__ Qf,
                                                     const __half* __restrict__ Kf,
                                                     const __half* __restrict__ VT) {
    extern __shared__ char shf[];
    const uint32_t sb = smem_u32(shf);
    const int tid = threadIdx.x, lane = tid & 31, wid = tid >> 5;
    const int qb = (int)gridDim.x - 1 - (int)blockIdx.x;
    const int h = blockIdx.y, b = blockIdx.z;
    const int q0 = qb * 128;
    const int wm0 = wid * 16;
    const float scale = 0.08838834764831845f;
    const float L2E = 1.4426950408889634f;

    const __half* Qg = Qf + (size_t)(b * SQ + q0) * HID + h * HD;
#pragma unroll
    for (int it = 0; it < 8; it++) {
        int idx = tid + it * 256;
        int r = idx >> 4, c8 = (idx & 15) << 3;
        cp16(sb + (uint32_t)(OFF_Q + r * FKS + c8) * 2, Qg + (size_t)r * HID + c8);
    }

    const __half* Kg0 = Kf + (size_t)(b * SQ) * HID + h * HD;
    const __half* Vg0 = VT + (size_t)((b * NHEAD + h) * HD) * SQ;

    {
#pragma unroll
        for (int it = 0; it < 4; it++) {
            int u = tid + it * 256;
            int r = u >> 4, c8 = (u & 15) << 3;
            cp16(sb + (uint32_t)(OFF_K0 + r * FKS + c8) * 2, Kg0 + (size_t)r * HID + c8);
        }
#pragma unroll
        for (int it = 0; it < 4; it++) {
            int u = tid + it * 256;
            int d = u >> 3, c8 = (u & 7) << 3;
            cp16(sb + (uint32_t)(OFF_V0 + d * FVS + c8) * 2, Vg0 + (size_t)d * SQ + c8);
        }
        cp_commit();
    }

    const uint32_t aBase = sb + 2u * (OFF_Q + (wm0 + (lane & 15)) * FKS + ((lane >> 4) << 3));
    const int krow = (lane & 7) + ((lane >> 4) << 3);
    uint32_t kBase[2], vBase[2];
#pragma unroll
    for (int bu = 0; bu < 2; bu++) {
        kBase[bu] = sb + 2u * (OFF_K0 + bu * KVSTG + krow * FKS + (lane & 8));
        vBase[bu] = sb + 2u * (OFF_V0 + bu * KVSTG + krow * FVS + (lane & 8));
    }

    float acc_o[16][4];
#pragma unroll
    for (int i = 0; i < 16; i++)
#pragma unroll
        for (int j = 0; j < 4; j++) acc_o[i][j] = 0.0f;
    float m0r = -1e30f, m1r = -1e30f, l0r = 0.0f, l1r = 0.0f;

    const int kb_max = 2 * qb + 1;
    const int r0g = q0 + wm0 + (lane >> 2);
    const int r1g = r0g + 8;

    for (int kb = 0; kb <= kb_max; kb++) {
        const int k0 = kb * 64;
        cp_wait<0>();
        __syncthreads();

        if (kb < kb_max) {
            const int kn = (kb + 1) * 64;
            const uint32_t bo = (uint32_t)(((kb + 1) & 1) * KVSTG) * 2;
#pragma unroll
            for (int it = 0; it < 4; it++) {
                int u = tid + it * 256;
                int r = u >> 4, c8 = (u & 15) << 3;
                cp16(sb + (uint32_t)(OFF_K0 + r * FKS + c8) * 2 + bo,
                     Kg0 + (size_t)(kn + r) * HID + c8);
            }
#pragma unroll
            for (int it = 0; it < 4; it++) {
                int u = tid + it * 256;
                int d = u >> 3, c8 = (u & 7) << 3;
                cp16(sb + (uint32_t)(OFF_V0 + d * FVS + c8) * 2 + bo,
                     Vg0 + (size_t)d * SQ + kn + c8);
            }
            cp_commit();
        }

        if (k0 > q0 + wm0) continue;
        const uint32_t kB = kBase[kb & 1], vB = vBase[kb & 1];

        float accs[8][4];
#pragma unroll
        for (int i = 0; i < 8; i++)
#pragma unroll
            for (int j = 0; j < 4; j++) accs[i][j] = 0.0f;
#pragma unroll
        for (int ks = 0; ks < 8; ks++) {
            uint32_t qh[4];
            ldm_x4(qh, aBase + ks * 32);
            uint32_t kk4[4][4];
#pragma unroll
            for (int ng = 0; ng < 4; ng++)
                ldm_x4(kk4[ng], kB + (uint32_t)(ng * 16 * FKS) * 2 + ks * 32);
#pragma unroll
            for (int ng = 0; ng < 4; ng++) {
                mma_f16(accs[2 * ng],     qh, kk4[ng][0], kk4[ng][1]);
                mma_f16(accs[2 * ng + 1], qh, kk4[ng][2], kk4[ng][3]);
            }
        }

#pragma unroll
        for (int nt = 0; nt < 8; nt++) {
            int cb = k0 + nt * 8 + (lane & 3) * 2;
            accs[nt][0] = accs[nt][0] * scale + ((cb     > r0g) ? -1e9f : 0.0f);
            accs[nt][1] = accs[nt][1] * scale + ((cb + 1 > r0g) ? -1e9f : 0.0f);
            accs[nt][2] = accs[nt][2] * scale + ((cb     > r1g) ? -1e9f : 0.0f);
            accs[nt][3] = accs[nt][3] * scale + ((cb + 1 > r1g) ? -1e9f : 0.0f);
        }

        float mx0 = -1e30f, mx1 = -1e30f;
#pragma unroll
        for (int nt = 0; nt < 8; nt++) {
            mx0 = fmaxf(mx0, fmaxf(accs[nt][0], accs[nt][1]));
            mx1 = fmaxf(mx1, fmaxf(accs[nt][2], accs[nt][3]));
        }
        mx0 = fmaxf(mx0, __shfl_xor_sync(0xffffffffu, mx0, 1));
        mx0 = fmaxf(mx0, __shfl_xor_sync(0xffffffffu, mx0, 2));
        mx1 = fmaxf(mx1, __shfl_xor_sync(0xffffffffu, mx1, 1));
        mx1 = fmaxf(mx1, __shfl_xor_sync(0xffffffffu, mx1, 2));
        float mn0 = fmaxf(m0r, mx0), mn1 = fmaxf(m1r, mx1);
        float al0 = __expf(m0r - mn0), al1 = __expf(m1r - mn1);
        m0r = mn0; m1r = mn1;

        /* f16x2 exp: p = 2^((s-m)*log2e); results ARE the fp16 P fragments */
        uint32_t pe[8][2];
        float rs0 = 0.0f, rs1 = 0.0f;
        const float c0 = -mn0 * L2E, c1 = -mn1 * L2E;
#pragma unroll
        for (int nt = 0; nt < 8; nt++) {
            pe[nt][0] = ex2_h2(fmaf(accs[nt][0], L2E, c0), fmaf(accs[nt][1], L2E, c0));
            pe[nt][1] = ex2_h2(fmaf(accs[nt][2], L2E, c1), fmaf(accs[nt][3], L2E, c1));
            float2 f01 = __half22float2(*(__half2*)&pe[nt][0]);
            float2 f23 = __half22float2(*(__half2*)&pe[nt][1]);
            rs0 += f01.x + f01.y;
            rs1 += f23.x + f23.y;
        }
        rs0 += __shfl_xor_sync(0xffffffffu, rs0, 1);
        rs0 += __shfl_xor_sync(0xffffffffu, rs0, 2);
        rs1 += __shfl_xor_sync(0xffffffffu, rs1, 1);
        rs1 += __shfl_xor_sync(0xffffffffu, rs1, 2);
        l0r = l0r * al0 + rs0;
        l1r = l1r * al1 + rs1;
#pragma unroll
        for (int i = 0; i < 16; i++) {
            acc_o[i][0] *= al0; acc_o[i][1] *= al0;
            acc_o[i][2] *= al1; acc_o[i][3] *= al1;
        }

        /* P fragments directly from pe */
        uint32_t ph[4][4];
#pragma unroll
        for (int kk = 0; kk < 4; kk++) {
            ph[kk][0] = pe[2 * kk][0];
            ph[kk][1] = pe[2 * kk][1];
            ph[kk][2] = pe[2 * kk + 1][0];
            ph[kk][3] = pe[2 * kk + 1][1];
        }

#pragma unroll
        for (int kk = 0; kk < 4; kk++) {
#pragma unroll
            for (int gb = 0; gb < 8; gb += 4) {
                uint32_t vt[4][4];
#pragma unroll
                for (int g = 0; g < 4; g++)
                    ldm_x4(vt[g], vB + (uint32_t)((gb + g) * 16 * FVS) * 2 + kk * 32);
#pragma unroll
                for (int g = 0; g < 4; g++) {
                    mma_f16(acc_o[2 * (gb + g)],     ph[kk], vt[g][0], vt[g][1]);
                    mma_f16(acc_o[2 * (gb + g) + 1], ph[kk], vt[g][2], vt[g][3]);
                }
            }
        }
    }

    float inv0 = 1.0f / l0r, inv1 = 1.0f / l1r;
    size_t base0 = (size_t)(b * SQ + r0g) * HID + h * HD;
    size_t base1 = base0 + (size_t)8 * HID;
#pragma unroll
    for (int nto = 0; nto < 16; nto++) {
        int c = nto * 8 + (lane & 3) * 2;
        *(uint32_t*)(g_Af + base0 + c) = pack_h(acc_o[nto][0] * inv0, acc_o[nto][1] * inv0);
        *(uint32_t*)(g_Af + base1 + c) = pack_h(acc_o[nto][2] * inv1, acc_o[nto][3] * inv1);
    }
}

/* ---------------- launcher ---------------------------------------------- */
extern "C" void kernel_launch(void* const* d_in, const int* in_sizes, int n_in,
                              void* d_out, int out_size) {
    (void)n_in; (void)out_size;
    const float* x   = (const float*)d_in[0];
    const float* cpq = (const float*)d_in[1];
    const float* cpk = (const float*)d_in[2];
    const float* cpv = (const float*)d_in[3];
    const float* cpo = (const float*)d_in[4];
    float* out = (float*)d_out;
    int ncp = in_sizes[1];

    __half *pWf, *pXf, *pAf, *pQf, *pKf, *pVT;
    float *pV;
    cudaGetSymbolAddress((void**)&pWf, g_Wf);
    cudaGetSymbolAddress((void**)&pXf, g_Xf);
    cudaGetSymbolAddress((void**)&pAf, g_Af);
    cudaGetSymbolAddress((void**)&pQf, g_Qf);
    cudaGetSymbolAddress((void**)&pKf, g_Kf);
    cudaGetSymbolAddress((void**)&pV,  g_V);
    cudaGetSymbolAddress((void**)&pVT, g_VT);

    build_weights<<<(NW + 255) / 256, 256>>>(cpq, cpk, cpv, cpo, ncp);
    split_x<<<(MROWS * HID / 4 + 255) / 256, 256>>>(x);

    cudaFuncSetAttribute(gemm_hmma, cudaFuncAttributeMaxDynamicSharedMemorySize,
                         GEMM_SMEM);
    gemm_hmma<<<dim3(HID / 128, MROWS / 128, 3), 256, GEMM_SMEM>>>(
        pXf, pWf, pQf, pKf, pV, 1);

    vtrans<<<dim3(SQ / 32, HD / 32, NB * NHEAD), dim3(32, 8)>>>(pV);

    cudaFuncSetAttribute(flash_hmma, cudaFuncAttributeMaxDynamicSharedMemorySize,
                         FL_SMEM);
    flash_hmma<<<dim3(SQ / 128, NHEAD, NB), 256, FL_SMEM>>>(pQf, pKf, pVT);

    gemm_hmma<<<dim3(HID / 128, MROWS / 128, 1), 256, GEMM_SMEM>>>(
        pAf, pWf + 3 * (size_t)NW, (__half*)0, (__half*)0, out, 0);
}